// round 1
// baseline (speedup 1.0000x reference)
#include <cuda_runtime.h>
#include <math.h>

#define B_    128
#define N_    196
#define ENC_  2048
#define DEC_  512
#define ATT_  512
#define M_    (B_ * N_)      // 25088 rows, divisible by 64 exactly (392 tiles)

// ---- scratch (no allocations allowed) ----
__device__ float g_att2[B_ * ATT_];       // [128, 512]
__device__ float g_epart[M_ * 8];         // partial e per (m, a-chunk)

// ============================================================
// Kernel 1: att2[b][a] = decoder_hidden[b] . W_dec[:,a] + b_dec[a]
// ============================================================
__global__ void att2_kernel(const float* __restrict__ dec,
                            const float* __restrict__ Wdec,
                            const float* __restrict__ bdec) {
    __shared__ float ds[DEC_];
    int b = blockIdx.x;
    int a = threadIdx.x;           // 512 threads
    ds[a] = dec[b * DEC_ + a];
    __syncthreads();
    float acc = bdec[a];
#pragma unroll 8
    for (int d = 0; d < DEC_; d++)
        acc += ds[d] * Wdec[d * ATT_ + a];
    g_att2[b * ATT_ + a] = acc;
}

// ============================================================
// Kernel 2: fused big GEMM + bias + att2 + relu + dot(W_full)
//   A = encoder_out viewed as [25088, 2048]
//   B = W_enc [2048, 512]
//   tile: 64 (m) x 64 (a) x 16 (k), 256 threads, 4x4 microtile
//   epilogue reduces the 64 a-columns to one partial-e per row.
// ============================================================
__global__ void gemm_e_kernel(const float* __restrict__ enc,
                              const float* __restrict__ Wenc,
                              const float* __restrict__ benc,
                              const float* __restrict__ Wfull) {
    __shared__ float As[16][68];   // k-major, padded (16B-aligned float4 reads)
    __shared__ float Bs[16][68];
    __shared__ float red[64][17];

    const int mtile  = blockIdx.x;       // 0..391
    const int achunk = blockIdx.y;       // 0..7
    const int m0 = mtile * 64;
    const int a0 = achunk * 64;

    const int tid = threadIdx.x;         // 256
    const int tx = tid & 15;
    const int ty = tid >> 4;

    // global-load lane mapping
    const int arow = tid >> 2;           // 0..63
    const int akc  = (tid & 3) * 4;      // 0,4,8,12
    const int bk   = tid >> 4;           // 0..15
    const int ba   = (tid & 15) * 4;     // 0..60

    const float* Ap = enc + (size_t)(m0 + arow) * ENC_ + akc;
    const float* Bp = Wenc + (size_t)bk * ATT_ + a0 + ba;

    float acc[4][4];
#pragma unroll
    for (int i = 0; i < 4; i++)
#pragma unroll
        for (int j = 0; j < 4; j++) acc[i][j] = 0.f;

    for (int k0 = 0; k0 < ENC_; k0 += 16) {
        float4 av = *(const float4*)(Ap + k0);
        As[akc + 0][arow] = av.x;
        As[akc + 1][arow] = av.y;
        As[akc + 2][arow] = av.z;
        As[akc + 3][arow] = av.w;
        float4 bv = *(const float4*)(Bp + (size_t)k0 * ATT_);
        *(float4*)&Bs[bk][ba] = bv;
        __syncthreads();

#pragma unroll
        for (int kk = 0; kk < 16; kk++) {
            float4 a4 = *(const float4*)&As[kk][ty * 4];
            float4 b4 = *(const float4*)&Bs[kk][tx * 4];
            float avr[4] = {a4.x, a4.y, a4.z, a4.w};
            float bvr[4] = {b4.x, b4.y, b4.z, b4.w};
#pragma unroll
            for (int i = 0; i < 4; i++)
#pragma unroll
                for (int j = 0; j < 4; j++)
                    acc[i][j] += avr[i] * bvr[j];
        }
        __syncthreads();
    }

    // epilogue: v = relu(acc + b_enc[a] + att2[b][a]); partial e = sum v*W_full[a]
#pragma unroll
    for (int i = 0; i < 4; i++) {
        int m = m0 + ty * 4 + i;
        int b = m / N_;
        float p = 0.f;
#pragma unroll
        for (int j = 0; j < 4; j++) {
            int a = a0 + tx * 4 + j;
            float v = acc[i][j] + benc[a] + g_att2[b * ATT_ + a];
            v = fmaxf(v, 0.f);
            p += v * Wfull[a];
        }
        red[ty * 4 + i][tx] = p;
    }
    __syncthreads();
    if (tid < 64) {
        float s = 0.f;
#pragma unroll
        for (int t = 0; t < 16; t++) s += red[tid][t];
        g_epart[(size_t)(m0 + tid) * 8 + achunk] = s;
    }
}

// ============================================================
// Kernel 3: e = sum(partials) + b_full; softmax over n -> alpha
// ============================================================
__global__ void softmax_kernel(float* __restrict__ out_alpha,
                               const float* __restrict__ bfull_p) {
    __shared__ float e_s[N_];
    __shared__ float red[256];
    int b = blockIdx.x;
    int tid = threadIdx.x;   // 256
    float bfull = *bfull_p;

    float ev = -INFINITY;
    if (tid < N_) {
        const float* p = &g_epart[(size_t)(b * N_ + tid) * 8];
        float s = bfull;
#pragma unroll
        for (int c = 0; c < 8; c++) s += p[c];
        e_s[tid] = s;
        ev = s;
    }
    red[tid] = ev;
    __syncthreads();
#pragma unroll
    for (int off = 128; off > 0; off >>= 1) {
        if (tid < off) red[tid] = fmaxf(red[tid], red[tid + off]);
        __syncthreads();
    }
    float mx = red[0];
    __syncthreads();

    float ex = 0.f;
    if (tid < N_) {
        ex = expf(e_s[tid] - mx);
        e_s[tid] = ex;
    }
    red[tid] = ex;
    __syncthreads();
#pragma unroll
    for (int off = 128; off > 0; off >>= 1) {
        if (tid < off) red[tid] += red[tid + off];
        __syncthreads();
    }
    float inv = 1.f / red[0];
    if (tid < N_) out_alpha[b * N_ + tid] = e_s[tid] * inv;
}

// ============================================================
// Kernel 4: awe[b][e] = sum_n enc[b][n][e] * alpha[b][n]
// ============================================================
__global__ void awe_kernel(const float* __restrict__ enc,
                           const float* __restrict__ alpha,
                           float* __restrict__ out) {
    __shared__ float al[N_];
    int b = blockIdx.y;
    int e = blockIdx.x * 256 + threadIdx.x;   // grid.x = 8
    if (threadIdx.x < N_) al[threadIdx.x] = alpha[b * N_ + threadIdx.x];
    __syncthreads();

    const float* p = enc + (size_t)b * N_ * ENC_ + e;
    float acc = 0.f;
#pragma unroll 4
    for (int n = 0; n < N_; n++)
        acc += al[n] * p[(size_t)n * ENC_];
    out[(size_t)b * ENC_ + e] = acc;
}

// ============================================================
extern "C" void kernel_launch(void* const* d_in, const int* in_sizes, int n_in,
                              void* d_out, int out_size) {
    const float* enc   = (const float*)d_in[0];  // [B, N, ENC]
    const float* dech  = (const float*)d_in[1];  // [B, DEC]
    const float* Wenc  = (const float*)d_in[2];  // [ENC, ATT]
    const float* benc  = (const float*)d_in[3];  // [ATT]
    const float* Wdec  = (const float*)d_in[4];  // [DEC, ATT]
    const float* bdec  = (const float*)d_in[5];  // [ATT]
    const float* Wfull = (const float*)d_in[6];  // [ATT]
    const float* bfull = (const float*)d_in[7];  // scalar

    float* out       = (float*)d_out;
    float* out_awe   = out;                      // [B, ENC] first (tuple order)
    float* out_alpha = out + (size_t)B_ * ENC_;  // [B, N] second

    att2_kernel<<<B_, ATT_>>>(dech, Wdec, bdec);

    dim3 g2(M_ / 64, ATT_ / 64);                 // 392 x 8
    gemm_e_kernel<<<g2, 256>>>(enc, Wenc, benc, Wfull);

    softmax_kernel<<<B_, 256>>>(out_alpha, bfull);

    dim3 g4(ENC_ / 256, B_);                     // 8 x 128
    awe_kernel<<<g4, 256>>>(enc, out_alpha, out_awe);
}

// round 2
// speedup vs baseline: 2.3653x; 2.3653x over previous
#include <cuda_runtime.h>
#include <cuda_bf16.h>
#include <stdint.h>
#include <math.h>

#define B_    128
#define N_    196
#define ENC_  2048
#define DEC_  512
#define ATT_  512
#define M_    (B_ * N_)          // 25088 rows
#define FM_TOT (M_ / 16)         // 1568 m-fragments
#define KF_TOT (ENC_ / 16)       // 128 k16 fragments
#define FN_TOT (ATT_ / 8)        // 64  n8 fragments

// ---- scratch (__device__ globals: the sanctioned no-alloc workaround) ----
__device__ float    g_att2[B_ * ATT_];            // [128, 512]
__device__ float    g_epart[M_ * 4];              // partial e per (m, n-chunk)
__device__ uint32_t g_Ahi[FM_TOT * KF_TOT * 128]; // fragment-packed bf16-hi of enc
__device__ uint32_t g_Alo[FM_TOT * KF_TOT * 128]; // fragment-packed bf16-lo of enc
__device__ uint32_t g_Bhi[FN_TOT * KF_TOT * 64];  // fragment-packed bf16-hi of W_enc
__device__ uint32_t g_Blo[FN_TOT * KF_TOT * 64];  // fragment-packed bf16-lo of W_enc

// ============================================================
// helpers
// ============================================================
__device__ __forceinline__ uint32_t pack_bf16x2(__nv_bfloat16 lo, __nv_bfloat16 hi) {
    __nv_bfloat162 p;
    p.x = lo; p.y = hi;          // .x = low 16 bits (lower k index)
    return *reinterpret_cast<uint32_t*>(&p);
}

__device__ __forceinline__ void split_bf16(float v, __nv_bfloat16& h, __nv_bfloat16& l) {
    h = __float2bfloat16(v);
    l = __float2bfloat16(v - __bfloat162float(h));
}

__device__ __forceinline__ void cp16(uint32_t smem_addr, const void* gptr) {
    asm volatile("cp.async.cg.shared.global [%0], [%1], 16;\n"
                 :: "r"(smem_addr), "l"(gptr));
}
__device__ __forceinline__ void cp_commit() {
    asm volatile("cp.async.commit_group;\n");
}
template <int NN>
__device__ __forceinline__ void cp_wait() {
    asm volatile("cp.async.wait_group %0;\n" :: "n"(NN));
}

__device__ __forceinline__ void mma16816(float c[4], const uint32_t a[4], const uint32_t b[2]) {
    asm volatile(
        "mma.sync.aligned.m16n8k16.row.col.f32.bf16.bf16.f32 "
        "{%0,%1,%2,%3}, {%4,%5,%6,%7}, {%8,%9}, {%0,%1,%2,%3};\n"
        : "+f"(c[0]), "+f"(c[1]), "+f"(c[2]), "+f"(c[3])
        : "r"(a[0]), "r"(a[1]), "r"(a[2]), "r"(a[3]),
          "r"(b[0]), "r"(b[1]));
}

// ============================================================
// Kernel 1: att2[b][a] = decoder_hidden[b] . W_dec[:,a] + b_dec[a]
// ============================================================
__global__ void att2_kernel(const float* __restrict__ dec,
                            const float* __restrict__ Wdec,
                            const float* __restrict__ bdec) {
    __shared__ float ds[DEC_];
    int b = blockIdx.x;
    int a = threadIdx.x;           // 512 threads
    ds[a] = dec[b * DEC_ + a];
    __syncthreads();
    float acc = bdec[a];
#pragma unroll 8
    for (int d = 0; d < DEC_; d++)
        acc += ds[d] * Wdec[d * ATT_ + a];
    g_att2[b * ATT_ + a] = acc;
}

// ============================================================
// Prepack A: enc [25088, 2048] fp32 -> fragment-major bf16 hi/lo
// Layout: [fm][kf][reg][lane], one u32 = two k-adjacent bf16.
// mma m16n8k16 A-frag mapping:
//   reg0: row g,   k tig*2..+1      reg1: row g+8, k tig*2..+1
//   reg2: row g,   k tig*2+8..+9    reg3: row g+8, k tig*2+8..+9
// ============================================================
__global__ void prepackA(const float* __restrict__ enc) {
    int idx = blockIdx.x * 256 + threadIdx.x;   // < 25690112
    int lane = idx & 31;
    int reg  = (idx >> 5) & 3;
    int kf   = (idx >> 7) & 127;
    int fm   = idx >> 14;
    int m = fm * 16 + (reg & 1) * 8 + (lane >> 2);
    int k = kf * 16 + (reg >> 1) * 8 + (lane & 3) * 2;
    float2 v = *reinterpret_cast<const float2*>(enc + (size_t)m * ENC_ + k);
    __nv_bfloat16 h0, l0, h1, l1;
    split_bf16(v.x, h0, l0);
    split_bf16(v.y, h1, l1);
    g_Ahi[idx] = pack_bf16x2(h0, h1);
    g_Alo[idx] = pack_bf16x2(l0, l1);
}

// ============================================================
// Prepack B: W_enc [2048, 512] fp32 -> fragment-major bf16 hi/lo
// Layout: [fn][kf][reg][lane].
//   reg0: k tig*2..+1, n g     reg1: k tig*2+8..+9, n g
// ============================================================
__global__ void prepackB(const float* __restrict__ Wenc) {
    int idx = blockIdx.x * 256 + threadIdx.x;   // < 524288
    int lane = idx & 31;
    int reg  = (idx >> 5) & 1;
    int kf   = (idx >> 6) & 127;
    int fn   = idx >> 13;
    int n = fn * 8 + (lane >> 2);
    int k = kf * 16 + reg * 8 + (lane & 3) * 2;
    float v0 = Wenc[(size_t)k * ATT_ + n];
    float v1 = Wenc[(size_t)(k + 1) * ATT_ + n];
    __nv_bfloat16 h0, l0, h1, l1;
    split_bf16(v0, h0, l0);
    split_bf16(v1, h1, l1);
    g_Bhi[idx] = pack_bf16x2(h0, h1);
    g_Blo[idx] = pack_bf16x2(l0, l1);
}

// ============================================================
// Kernel 2: tensor-core GEMM (3-term bf16 split) + fused epilogue
//   block tile: 128(m) x 128(n) x 32(k), 256 threads, 8 warps (4Mx2N)
//   warp tile:  32 x 64  -> 2 m-frags x 8 n-frags, acc 64 f32/thread
//   smem: 2-stage cp.async pipeline, 64KB dynamic
//   As stage: [fm8][kf2][hilo2][reg4][lane32] u32  (4096 u32 / stage)
//   Bs stage: [fn16][kf2][hilo2][reg2][lane32] u32 (4096 u32 / stage)
// ============================================================
__global__ __launch_bounds__(256, 1)
void gemm_e_kernel(const float* __restrict__ benc,
                   const float* __restrict__ Wfull) {
    extern __shared__ uint32_t sm[];   // 16384 u32 = 64KB; As=[0,8192), Bs=[8192,16384)
    const int tid = threadIdx.x;
    const int mtile  = blockIdx.x;     // 0..195
    const int nchunk = blockIdx.y;     // 0..3
    const int lane = tid & 31, wid = tid >> 5;
    const int warpM = wid & 3, warpN = wid >> 2;

    const uint32_t smbase =
        (uint32_t)__cvta_generic_to_shared(sm);

    float acc[2][8][4];
#pragma unroll
    for (int i = 0; i < 2; i++)
#pragma unroll
        for (int j = 0; j < 8; j++)
#pragma unroll
            for (int q = 0; q < 4; q++) acc[i][j][q] = 0.f;

    // ---- async copy of one k-step (32 k) into stage st ----
    auto issue = [&](int ks, int st) {
#pragma unroll
        for (int i = 0; i < 8; i++) {
            int c = tid + i * 256;            // 0..2047
            uint32_t dst;
            const uint32_t* src;
            if (i < 4) {                      // A region: chunks 0..1023
                int fm = c >> 7, kf = (c >> 6) & 1, hilo = (c >> 5) & 1, sub = c & 31;
                const uint32_t* base = hilo ? g_Alo : g_Ahi;
                src = base + (((size_t)(mtile * 8 + fm) * KF_TOT + (ks * 2 + kf)) * 128 + sub * 4);
                dst = smbase + (uint32_t)(st * 4096 + ((fm * 2 + kf) * 2 + hilo) * 128 + sub * 4) * 4u;
            } else {                          // B region: chunks 1024..2047
                int d = c - 1024;
                int fn = d >> 6, kf = (d >> 5) & 1, hilo = (d >> 4) & 1, sub = d & 15;
                const uint32_t* base = hilo ? g_Blo : g_Bhi;
                src = base + (((size_t)(nchunk * 16 + fn) * KF_TOT + (ks * 2 + kf)) * 64 + sub * 4);
                dst = smbase + (uint32_t)(8192 + st * 4096 + ((fn * 2 + kf) * 2 + hilo) * 64 + sub * 4) * 4u;
            }
            cp16(dst, src);
        }
        cp_commit();
    };

    issue(0, 0);

    const int NKS = ENC_ / 32;   // 64
    for (int ks = 0; ks < NKS; ks++) {
        int st = ks & 1;
        if (ks + 1 < NKS) {
            issue(ks + 1, st ^ 1);
            cp_wait<1>();
        } else {
            cp_wait<0>();
        }
        __syncthreads();

#pragma unroll
        for (int kf = 0; kf < 2; kf++) {
            uint32_t a[2][2][4];   // [fm][hilo][reg]
            uint32_t b[8][2][2];   // [fn][hilo][reg]
#pragma unroll
            for (int fm = 0; fm < 2; fm++) {
                int fmAbs = warpM * 2 + fm;
#pragma unroll
                for (int h = 0; h < 2; h++) {
                    int off = st * 4096 + ((fmAbs * 2 + kf) * 2 + h) * 128 + lane;
#pragma unroll
                    for (int r = 0; r < 4; r++)
                        a[fm][h][r] = sm[off + r * 32];
                }
            }
#pragma unroll
            for (int fn = 0; fn < 8; fn++) {
                int fnAbs = warpN * 8 + fn;
#pragma unroll
                for (int h = 0; h < 2; h++) {
                    int off = 8192 + st * 4096 + ((fnAbs * 2 + kf) * 2 + h) * 64 + lane;
#pragma unroll
                    for (int r = 0; r < 2; r++)
                        b[fn][h][r] = sm[off + r * 32];
                }
            }
#pragma unroll
            for (int fm = 0; fm < 2; fm++)
#pragma unroll
                for (int fn = 0; fn < 8; fn++) {
                    mma16816(acc[fm][fn], a[fm][0], b[fn][0]);  // hi*hi
                    mma16816(acc[fm][fn], a[fm][1], b[fn][0]);  // lo*hi
                    mma16816(acc[fm][fn], a[fm][0], b[fn][1]);  // hi*lo
                }
        }
        __syncthreads();
    }

    // ---- fused epilogue: v = relu(acc + b_enc + att2); e += v * W_full ----
    const int g = lane >> 2, tig = lane & 3;
    const int m0g = mtile * 128;
    float ep[2][2] = {{0.f, 0.f}, {0.f, 0.f}};   // [fm][half]
#pragma unroll
    for (int fm = 0; fm < 2; fm++) {
        int r0 = warpM * 32 + fm * 16 + g;
        int b0 = (m0g + r0) / N_;
        int b1 = (m0g + r0 + 8) / N_;
#pragma unroll
        for (int fn = 0; fn < 8; fn++) {
            int col = warpN * 64 + fn * 8 + tig * 2;
            int a0i = nchunk * 128 + col;
            int a1i = a0i + 1;
            float w0 = Wfull[a0i], w1 = Wfull[a1i];
            float be0 = benc[a0i], be1 = benc[a1i];
            float t2_00 = g_att2[b0 * ATT_ + a0i];
            float t2_01 = g_att2[b0 * ATT_ + a1i];
            float t2_10 = g_att2[b1 * ATT_ + a0i];
            float t2_11 = g_att2[b1 * ATT_ + a1i];
            ep[fm][0] += fmaxf(acc[fm][fn][0] + be0 + t2_00, 0.f) * w0;
            ep[fm][0] += fmaxf(acc[fm][fn][1] + be1 + t2_01, 0.f) * w1;
            ep[fm][1] += fmaxf(acc[fm][fn][2] + be0 + t2_10, 0.f) * w0;
            ep[fm][1] += fmaxf(acc[fm][fn][3] + be1 + t2_11, 0.f) * w1;
        }
    }
    // reduce across tig (lanes g*4 .. g*4+3)
#pragma unroll
    for (int off = 1; off <= 2; off <<= 1) {
#pragma unroll
        for (int fm = 0; fm < 2; fm++) {
            ep[fm][0] += __shfl_xor_sync(0xffffffffu, ep[fm][0], off);
            ep[fm][1] += __shfl_xor_sync(0xffffffffu, ep[fm][1], off);
        }
    }
    float* e_red = reinterpret_cast<float*>(sm);   // [128][2], overlays pipeline smem
    if (tig == 0) {
#pragma unroll
        for (int fm = 0; fm < 2; fm++) {
            int r0 = warpM * 32 + fm * 16 + g;
            e_red[r0 * 2 + warpN]       = ep[fm][0];
            e_red[(r0 + 8) * 2 + warpN] = ep[fm][1];
        }
    }
    __syncthreads();
    if (tid < 128) {
        float e = e_red[tid * 2 + 0] + e_red[tid * 2 + 1];
        g_epart[(size_t)(m0g + tid) * 4 + nchunk] = e;
    }
}

// ============================================================
// Kernel 3: e = sum(partials) + b_full; softmax over n -> alpha
// ============================================================
__global__ void softmax_kernel(float* __restrict__ out_alpha,
                               const float* __restrict__ bfull_p) {
    __shared__ float e_s[N_];
    __shared__ float red[256];
    int b = blockIdx.x;
    int tid = threadIdx.x;   // 256
    float bfull = *bfull_p;

    float ev = -INFINITY;
    if (tid < N_) {
        const float* p = &g_epart[(size_t)(b * N_ + tid) * 4];
        float s = bfull + p[0] + p[1] + p[2] + p[3];
        e_s[tid] = s;
        ev = s;
    }
    red[tid] = ev;
    __syncthreads();
#pragma unroll
    for (int off = 128; off > 0; off >>= 1) {
        if (tid < off) red[tid] = fmaxf(red[tid], red[tid + off]);
        __syncthreads();
    }
    float mx = red[0];
    __syncthreads();

    float ex = 0.f;
    if (tid < N_) {
        ex = expf(e_s[tid] - mx);
        e_s[tid] = ex;
    }
    red[tid] = ex;
    __syncthreads();
#pragma unroll
    for (int off = 128; off > 0; off >>= 1) {
        if (tid < off) red[tid] += red[tid + off];
        __syncthreads();
    }
    float inv = 1.f / red[0];
    if (tid < N_) out_alpha[b * N_ + tid] = e_s[tid] * inv;
}

// ============================================================
// Kernel 4: awe[b][e] = sum_n enc[b][n][e] * alpha[b][n]
// ============================================================
__global__ void awe_kernel(const float* __restrict__ enc,
                           const float* __restrict__ alpha,
                           float* __restrict__ out) {
    __shared__ float al[N_];
    int b = blockIdx.y;
    int e = blockIdx.x * 256 + threadIdx.x;   // grid.x = 8
    if (threadIdx.x < N_) al[threadIdx.x] = alpha[b * N_ + threadIdx.x];
    __syncthreads();

    const float* p = enc + (size_t)b * N_ * ENC_ + e;
    float acc = 0.f;
#pragma unroll 4
    for (int n = 0; n < N_; n++)
        acc += al[n] * p[(size_t)n * ENC_];
    out[(size_t)b * ENC_ + e] = acc;
}

// ============================================================
extern "C" void kernel_launch(void* const* d_in, const int* in_sizes, int n_in,
                              void* d_out, int out_size) {
    const float* enc   = (const float*)d_in[0];  // [B, N, ENC]
    const float* dech  = (const float*)d_in[1];  // [B, DEC]
    const float* Wenc  = (const float*)d_in[2];  // [ENC, ATT]
    const float* benc  = (const float*)d_in[3];  // [ATT]
    const float* Wdec  = (const float*)d_in[4];  // [DEC, ATT]
    const float* bdec  = (const float*)d_in[5];  // [ATT]
    const float* Wfull = (const float*)d_in[6];  // [ATT]
    const float* bfull = (const float*)d_in[7];  // scalar

    float* out       = (float*)d_out;
    float* out_awe   = out;                      // [B, ENC]
    float* out_alpha = out + (size_t)B_ * ENC_;  // [B, N]

    cudaFuncSetAttribute(gemm_e_kernel,
                         cudaFuncAttributeMaxDynamicSharedMemorySize, 65536);

    att2_kernel<<<B_, ATT_>>>(dech, Wdec, bdec);
    prepackA<<<FM_TOT * KF_TOT * 128 / 256, 256>>>(enc);
    prepackB<<<FN_TOT * KF_TOT * 64 / 256, 256>>>(Wenc);

    dim3 g2(M_ / 128, 4);                        // 196 x 4
    gemm_e_kernel<<<g2, 256, 65536>>>(benc, Wfull);

    softmax_kernel<<<B_, 256>>>(out_alpha, bfull);

    dim3 g4(ENC_ / 256, B_);                     // 8 x 128
    awe_kernel<<<g4, 256>>>(enc, out_alpha, out_awe);
}

// round 4
// speedup vs baseline: 2.4973x; 1.0558x over previous
#include <cuda_runtime.h>
#include <cuda_bf16.h>
#include <stdint.h>
#include <math.h>

#define B_    128
#define N_    196
#define ENC_  2048
#define DEC_  512
#define ATT_  512
#define M_    (B_ * N_)          // 25088 rows
#define FM_TOT (M_ / 16)         // 1568 m-fragments
#define KF_TOT (ENC_ / 16)       // 128 k16 fragments
#define FN_TOT (ATT_ / 8)        // 64  n8 fragments

// gemm tiling: block 128m x 64n x 32k, 3-stage cp.async, 2 CTAs/SM
#define NKS        64            // k-steps of 32
#define STAGE_U32  6144          // A 4096 + B 2048 u32 per stage
#define SMEM_BYTES (3 * STAGE_U32 * 4)   // 73728

// ---- scratch (__device__ globals: sanctioned no-alloc workaround) ----
__device__ float    g_att2[B_ * ATT_];
__device__ float    g_epart[M_ * 8];
__device__ uint32_t g_Ahi[FM_TOT * KF_TOT * 128];
__device__ uint32_t g_Alo[FM_TOT * KF_TOT * 128];
__device__ uint32_t g_Bhi[FN_TOT * KF_TOT * 64];
__device__ uint32_t g_Blo[FN_TOT * KF_TOT * 64];

// ============================================================
// helpers
// ============================================================
__device__ __forceinline__ uint32_t pack_bf16x2(__nv_bfloat16 lo, __nv_bfloat16 hi) {
    __nv_bfloat162 p; p.x = lo; p.y = hi;
    return *reinterpret_cast<uint32_t*>(&p);
}
__device__ __forceinline__ void split_bf16(float v, __nv_bfloat16& h, __nv_bfloat16& l) {
    h = __float2bfloat16(v);
    l = __float2bfloat16(v - __bfloat162float(h));
}
__device__ __forceinline__ void cp16(uint32_t saddr, const void* g) {
    asm volatile("cp.async.cg.shared.global [%0], [%1], 16;\n" :: "r"(saddr), "l"(g));
}
__device__ __forceinline__ void cp_commit() { asm volatile("cp.async.commit_group;\n"); }
template <int NN> __device__ __forceinline__ void cp_wait() {
    asm volatile("cp.async.wait_group %0;\n" :: "n"(NN));
}
__device__ __forceinline__ void mma16816(float c[4], const uint32_t a[4], const uint32_t b[2]) {
    asm volatile(
        "mma.sync.aligned.m16n8k16.row.col.f32.bf16.bf16.f32 "
        "{%0,%1,%2,%3}, {%4,%5,%6,%7}, {%8,%9}, {%0,%1,%2,%3};\n"
        : "+f"(c[0]), "+f"(c[1]), "+f"(c[2]), "+f"(c[3])
        : "r"(a[0]), "r"(a[1]), "r"(a[2]), "r"(a[3]),
          "r"(b[0]), "r"(b[1]));
}

// ============================================================
// Kernel 1: att2 = decoder_hidden @ W_dec + b_dec
// ============================================================
__global__ void att2_kernel(const float* __restrict__ dec,
                            const float* __restrict__ Wdec,
                            const float* __restrict__ bdec) {
    __shared__ float ds[DEC_];
    int b = blockIdx.x, a = threadIdx.x;
    ds[a] = dec[b * DEC_ + a];
    __syncthreads();
    float acc = bdec[a];
#pragma unroll 8
    for (int d = 0; d < DEC_; d++) acc += ds[d] * Wdec[d * ATT_ + a];
    g_att2[b * ATT_ + a] = acc;
}

// ============================================================
// Prepack A: enc fp32 [M][K] -> fragment-major bf16x2 hi/lo
//   layout [fm][kf][reg4][lane32]
// ============================================================
__global__ void prepackA(const float* __restrict__ enc) {
    int idx = blockIdx.x * 256 + threadIdx.x;
    int lane = idx & 31;
    int reg  = (idx >> 5) & 3;
    int kf   = (idx >> 7) & 127;
    int fm   = idx >> 14;
    int m = fm * 16 + (reg & 1) * 8 + (lane >> 2);
    int k = kf * 16 + (reg >> 1) * 8 + (lane & 3) * 2;
    float2 v = *reinterpret_cast<const float2*>(enc + (size_t)m * ENC_ + k);
    __nv_bfloat16 h0, l0, h1, l1;
    split_bf16(v.x, h0, l0);
    split_bf16(v.y, h1, l1);
    g_Ahi[idx] = pack_bf16x2(h0, h1);
    g_Alo[idx] = pack_bf16x2(l0, l1);
}

// ============================================================
// Prepack B: W_enc [K][N] -> fragment-major bf16x2 hi/lo
//   layout [fn][kf][reg2][lane32]
// ============================================================
__global__ void prepackB(const float* __restrict__ Wenc) {
    int idx = blockIdx.x * 256 + threadIdx.x;
    int lane = idx & 31;
    int reg  = (idx >> 5) & 1;
    int kf   = (idx >> 6) & 127;
    int fn   = idx >> 13;
    int n = fn * 8 + (lane >> 2);
    int k = kf * 16 + reg * 8 + (lane & 3) * 2;
    float v0 = Wenc[(size_t)k * ATT_ + n];
    float v1 = Wenc[(size_t)(k + 1) * ATT_ + n];
    __nv_bfloat16 h0, l0, h1, l1;
    split_bf16(v0, h0, l0);
    split_bf16(v1, h1, l1);
    g_Bhi[idx] = pack_bf16x2(h0, h1);
    g_Blo[idx] = pack_bf16x2(l0, l1);
}

// ============================================================
// Kernel 2: HMMA GEMM (3-term bf16 split) + fused epilogue
//   block 128m x 64n x 32k; 8 warps (4M x 2N), warp tile 32x32
//   grid (nchunk=8 fastest, mtile=196) for L2 reuse of A
// ============================================================
__global__ __launch_bounds__(256, 2)
void gemm_e_kernel(const float* __restrict__ benc,
                   const float* __restrict__ Wfull) {
    extern __shared__ uint32_t sm[];   // 3 stages x 6144 u32
    const int tid = threadIdx.x;
    const int lane = tid & 31, wid = tid >> 5;
    const int warpM = wid & 3, warpN = wid >> 2;   // 4M x 2N
    const int nchunk = blockIdx.x;     // 0..7
    const int mtile  = blockIdx.y;     // 0..195
    const int m0g = mtile * 128;

    const uint32_t smbase = (uint32_t)__cvta_generic_to_shared(sm);

    float acc[2][4][4];
#pragma unroll
    for (int i = 0; i < 2; i++)
#pragma unroll
        for (int j = 0; j < 4; j++)
#pragma unroll
            for (int q = 0; q < 4; q++) acc[i][j][q] = 0.f;

    // ---- async load of k-step ks into stage st: 1536 x 16B, 6/thread ----
    auto issue = [&](int ks, int st) {
        const uint32_t so = smbase + (uint32_t)(st * STAGE_U32) * 4u;
#pragma unroll
        for (int i = 0; i < 6; i++) {
            int c = i * 256 + tid;           // 0..1535
            uint32_t dst;
            const uint32_t* src;
            if (c < 1024) {                  // A: fm8 kf2 hilo2 sub32
                int fm = c >> 7, kf = (c >> 6) & 1, hilo = (c >> 5) & 1, sub = c & 31;
                const uint32_t* base = hilo ? g_Alo : g_Ahi;
                src = base + (((size_t)(mtile * 8 + fm) * KF_TOT + (ks * 2 + kf)) * 128 + sub * 4);
                dst = so + (uint32_t)(((fm * 2 + kf) * 2 + hilo) * 128 + sub * 4) * 4u;
            } else {                         // B: fn8 kf2 hilo2 sub16
                int d = c - 1024;
                int fn = d >> 6, kf = (d >> 5) & 1, hilo = (d >> 4) & 1, sub = d & 15;
                const uint32_t* base = hilo ? g_Blo : g_Bhi;
                src = base + (((size_t)(nchunk * 8 + fn) * KF_TOT + (ks * 2 + kf)) * 64 + sub * 4);
                dst = so + (uint32_t)(4096 + ((fn * 2 + kf) * 2 + hilo) * 64 + sub * 4) * 4u;
            }
            cp16(dst, src);
        }
        cp_commit();
    };

    issue(0, 0);
    issue(1, 1);
    issue(2, 2);

    for (int s = 0; s < NKS; s++) {
        const int st = s % 3;
        if (s + 3 < NKS)      cp_wait<2>();
        else if (s + 2 < NKS) cp_wait<2>();
        else if (s + 1 < NKS) cp_wait<1>();
        else                  cp_wait<0>();
        __syncthreads();

        const int sb = st * STAGE_U32;
#pragma unroll
        for (int kf = 0; kf < 2; kf++) {
            uint32_t a[2][2][4];   // [fm][hilo][reg]
            uint32_t b[4][2][2];   // [fn][hilo][reg]
#pragma unroll
            for (int fm = 0; fm < 2; fm++) {
                int fmAbs = warpM * 2 + fm;
#pragma unroll
                for (int h = 0; h < 2; h++) {
                    int off = sb + ((fmAbs * 2 + kf) * 2 + h) * 128 + lane;
#pragma unroll
                    for (int r = 0; r < 4; r++) a[fm][h][r] = sm[off + r * 32];
                }
            }
#pragma unroll
            for (int fn = 0; fn < 4; fn++) {
                int fnAbs = warpN * 4 + fn;
#pragma unroll
                for (int h = 0; h < 2; h++) {
                    int off = sb + 4096 + ((fnAbs * 2 + kf) * 2 + h) * 64 + lane;
#pragma unroll
                    for (int r = 0; r < 2; r++) b[fn][h][r] = sm[off + r * 32];
                }
            }
#pragma unroll
            for (int fm = 0; fm < 2; fm++)
#pragma unroll
                for (int fn = 0; fn < 4; fn++) {
                    mma16816(acc[fm][fn], a[fm][0], b[fn][0]);  // hi*hi
                    mma16816(acc[fm][fn], a[fm][1], b[fn][0]);  // lo*hi
                    mma16816(acc[fm][fn], a[fm][0], b[fn][1]);  // hi*lo
                }
        }
        __syncthreads();
        if (s + 3 < NKS) issue(s + 3, st);
    }

    // ---- fused epilogue ----
    const int g = lane >> 2, tig = lane & 3;
    float ep[2][2] = {{0.f, 0.f}, {0.f, 0.f}};
#pragma unroll
    for (int fm = 0; fm < 2; fm++) {
        int r0 = warpM * 32 + fm * 16 + g;
        int b0 = (m0g + r0) / N_;
        int b1 = (m0g + r0 + 8) / N_;
#pragma unroll
        for (int fn = 0; fn < 4; fn++) {
            int a0i = nchunk * 64 + warpN * 32 + fn * 8 + tig * 2;
            int a1i = a0i + 1;
            float w0 = Wfull[a0i], w1 = Wfull[a1i];
            float be0 = benc[a0i], be1 = benc[a1i];
            float t00 = g_att2[b0 * ATT_ + a0i];
            float t01 = g_att2[b0 * ATT_ + a1i];
            float t10 = g_att2[b1 * ATT_ + a0i];
            float t11 = g_att2[b1 * ATT_ + a1i];
            ep[fm][0] += fmaxf(acc[fm][fn][0] + be0 + t00, 0.f) * w0;
            ep[fm][0] += fmaxf(acc[fm][fn][1] + be1 + t01, 0.f) * w1;
            ep[fm][1] += fmaxf(acc[fm][fn][2] + be0 + t10, 0.f) * w0;
            ep[fm][1] += fmaxf(acc[fm][fn][3] + be1 + t11, 0.f) * w1;
        }
    }
#pragma unroll
    for (int off = 1; off <= 2; off <<= 1)
#pragma unroll
        for (int fm = 0; fm < 2; fm++) {
            ep[fm][0] += __shfl_xor_sync(0xffffffffu, ep[fm][0], off);
            ep[fm][1] += __shfl_xor_sync(0xffffffffu, ep[fm][1], off);
        }

    float* e_red = reinterpret_cast<float*>(sm);   // [128][2]
    if (tig == 0) {
#pragma unroll
        for (int fm = 0; fm < 2; fm++) {
            int r0 = warpM * 32 + fm * 16 + g;
            e_red[r0 * 2 + warpN]       = ep[fm][0];
            e_red[(r0 + 8) * 2 + warpN] = ep[fm][1];
        }
    }
    __syncthreads();
    if (tid < 128)
        g_epart[(size_t)(m0g + tid) * 8 + nchunk] = e_red[tid * 2] + e_red[tid * 2 + 1];
}

// ============================================================
// Kernel 3: softmax over n
// ============================================================
__global__ void softmax_kernel(float* __restrict__ out_alpha,
                               const float* __restrict__ bfull_p) {
    __shared__ float e_s[N_];
    __shared__ float red[256];
    int b = blockIdx.x, tid = threadIdx.x;
    float bfull = *bfull_p;

    float ev = -INFINITY;
    if (tid < N_) {
        const float* p = &g_epart[(size_t)(b * N_ + tid) * 8];
        float s = bfull;
#pragma unroll
        for (int c = 0; c < 8; c++) s += p[c];
        e_s[tid] = s; ev = s;
    }
    red[tid] = ev; __syncthreads();
#pragma unroll
    for (int off = 128; off > 0; off >>= 1) {
        if (tid < off) red[tid] = fmaxf(red[tid], red[tid + off]);
        __syncthreads();
    }
    float mx = red[0]; __syncthreads();
    float ex = 0.f;
    if (tid < N_) { ex = expf(e_s[tid] - mx); e_s[tid] = ex; }
    red[tid] = ex; __syncthreads();
#pragma unroll
    for (int off = 128; off > 0; off >>= 1) {
        if (tid < off) red[tid] += red[tid + off];
        __syncthreads();
    }
    float inv = 1.f / red[0];
    if (tid < N_) out_alpha[b * N_ + tid] = e_s[tid] * inv;
}

// ============================================================
// Kernel 4: awe[b][e] = sum_n enc[b][n][e] * alpha[b][n]  (float4)
// ============================================================
__global__ void awe_kernel(const float* __restrict__ enc,
                           const float* __restrict__ alpha,
                           float* __restrict__ out) {
    __shared__ float al[N_];
    int b = blockIdx.y;
    int e0 = (blockIdx.x * 256 + threadIdx.x) * 4;   // grid.x = 2
    if (threadIdx.x < N_) al[threadIdx.x] = alpha[b * N_ + threadIdx.x];
    __syncthreads();

    const float4* p = reinterpret_cast<const float4*>(enc + (size_t)b * N_ * ENC_ + e0);
    float4 acc = make_float4(0.f, 0.f, 0.f, 0.f);
#pragma unroll 4
    for (int n = 0; n < N_; n++) {
        float4 v = p[(size_t)n * (ENC_ / 4)];
        float a = al[n];
        acc.x += a * v.x; acc.y += a * v.y;
        acc.z += a * v.z; acc.w += a * v.w;
    }
    *reinterpret_cast<float4*>(out + (size_t)b * ENC_ + e0) = acc;
}

// ============================================================
extern "C" void kernel_launch(void* const* d_in, const int* in_sizes, int n_in,
                              void* d_out, int out_size) {
    const float* enc   = (const float*)d_in[0];
    const float* dech  = (const float*)d_in[1];
    const float* Wenc  = (const float*)d_in[2];
    const float* benc  = (const float*)d_in[3];
    const float* Wdec  = (const float*)d_in[4];
    const float* bdec  = (const float*)d_in[5];
    const float* Wfull = (const float*)d_in[6];
    const float* bfull = (const float*)d_in[7];

    float* out       = (float*)d_out;
    float* out_awe   = out;
    float* out_alpha = out + (size_t)B_ * ENC_;

    cudaFuncSetAttribute(gemm_e_kernel,
                         cudaFuncAttributeMaxDynamicSharedMemorySize, SMEM_BYTES);

    att2_kernel<<<B_, ATT_>>>(dech, Wdec, bdec);
    prepackA<<<FM_TOT * KF_TOT * 128 / 256, 256>>>(enc);
    prepackB<<<FN_TOT * KF_TOT * 64 / 256, 256>>>(Wenc);

    dim3 g2(8, 196);                           // nchunk fastest -> A L2 reuse
    gemm_e_kernel<<<g2, 256, SMEM_BYTES>>>(benc, Wfull);

    softmax_kernel<<<B_, 256>>>(out_alpha, bfull);

    dim3 g4(2, B_);
    awe_kernel<<<g4, 256>>>(enc, out_alpha, out_awe);
}

// round 5
// speedup vs baseline: 2.5446x; 1.0189x over previous
#include <cuda_runtime.h>
#include <cuda_bf16.h>
#include <stdint.h>
#include <math.h>

#define B_    128
#define N_    196
#define ENC_  2048
#define DEC_  512
#define ATT_  512
#define M_    (B_ * N_)          // 25088 rows
#define KF_TOT (ENC_ / 16)       // 128 k16 fragments
#define FN_TOT (ATT_ / 8)        // 64  n8 fragments

// gemm tiling: block 128m x 64n x 32k, 4-stage cp.async, 2 CTAs/SM
#define NKS        64            // k-steps of 32
#define STAGE_U32  6144          // A 4096 (raw fp32, swizzled) + B 2048 u32
#define NSTAGE     4
#define SMEM_BYTES (NSTAGE * STAGE_U32 * 4)   // 98304

// ---- scratch (__device__ globals: sanctioned no-alloc workaround) ----
__device__ float    g_att2[B_ * ATT_];
__device__ float    g_epart[M_ * 8];
__device__ uint32_t g_Bhi[FN_TOT * KF_TOT * 64];
__device__ uint32_t g_Blo[FN_TOT * KF_TOT * 64];

// ============================================================
// helpers
// ============================================================
__device__ __forceinline__ uint32_t pack_bf16x2(__nv_bfloat16 lo, __nv_bfloat16 hi) {
    __nv_bfloat162 p; p.x = lo; p.y = hi;
    return *reinterpret_cast<uint32_t*>(&p);
}
__device__ __forceinline__ void split_bf16(float v, __nv_bfloat16& h, __nv_bfloat16& l) {
    h = __float2bfloat16(v);
    l = __float2bfloat16(v - __bfloat162float(h));
}
__device__ __forceinline__ void cp16(uint32_t saddr, const void* g) {
    asm volatile("cp.async.cg.shared.global [%0], [%1], 16;\n" :: "r"(saddr), "l"(g));
}
__device__ __forceinline__ void cp_commit() { asm volatile("cp.async.commit_group;\n"); }
template <int NN> __device__ __forceinline__ void cp_wait() {
    asm volatile("cp.async.wait_group %0;\n" :: "n"(NN));
}
__device__ __forceinline__ void mma16816(float c[4], const uint32_t a[4], const uint32_t b[2]) {
    asm volatile(
        "mma.sync.aligned.m16n8k16.row.col.f32.bf16.bf16.f32 "
        "{%0,%1,%2,%3}, {%4,%5,%6,%7}, {%8,%9}, {%0,%1,%2,%3};\n"
        : "+f"(c[0]), "+f"(c[1]), "+f"(c[2]), "+f"(c[3])
        : "r"(a[0]), "r"(a[1]), "r"(a[2]), "r"(a[3]),
          "r"(b[0]), "r"(b[1]));
}
// pack two fp32 -> bf16x2 (first source -> high half)
__device__ __forceinline__ uint32_t cvt2bf(float fhi, float flo) {
    uint32_t r;
    asm("cvt.rn.bf16x2.f32 %0, %1, %2;" : "=r"(r) : "f"(fhi), "f"(flo));
    return r;
}

// ============================================================
// Kernel 1: att2 = decoder_hidden @ W_dec + b_dec
// ============================================================
__global__ void att2_kernel(const float* __restrict__ dec,
                            const float* __restrict__ Wdec,
                            const float* __restrict__ bdec) {
    __shared__ float ds[DEC_];
    int b = blockIdx.x, a = threadIdx.x;
    ds[a] = dec[b * DEC_ + a];
    __syncthreads();
    float acc = bdec[a];
#pragma unroll 8
    for (int d = 0; d < DEC_; d++) acc += ds[d] * Wdec[d * ATT_ + a];
    g_att2[b * ATT_ + a] = acc;
}

// ============================================================
// Prepack B: W_enc [K][N] -> fragment-major bf16x2 hi/lo (small, 4MB)
// ============================================================
__global__ void prepackB(const float* __restrict__ Wenc) {
    int idx = blockIdx.x * 256 + threadIdx.x;
    int lane = idx & 31;
    int reg  = (idx >> 5) & 1;
    int kf   = (idx >> 6) & 127;
    int fn   = idx >> 13;
    int n = fn * 8 + (lane >> 2);
    int k = kf * 16 + reg * 8 + (lane & 3) * 2;
    float v0 = Wenc[(size_t)k * ATT_ + n];
    float v1 = Wenc[(size_t)(k + 1) * ATT_ + n];
    __nv_bfloat16 h0, l0, h1, l1;
    split_bf16(v0, h0, l0);
    split_bf16(v1, h1, l1);
    g_Bhi[idx] = pack_bf16x2(h0, h1);
    g_Blo[idx] = pack_bf16x2(l0, l1);
}

// ============================================================
// Kernel 2: HMMA GEMM (3-term bf16 split, A split fused in-kernel)
//   block 128m x 64n x 32k; 8 warps (4M x 2N), warp tile 32x32
//   A: raw fp32 rows via cp.async, XOR-swizzled; split to hi/lo in regs
//   grid (nchunk=8 fastest, mtile=196) for L2 reuse of A
// ============================================================
__global__ __launch_bounds__(256, 2)
void gemm_e_kernel(const float* __restrict__ enc,
                   const float* __restrict__ benc,
                   const float* __restrict__ Wfull) {
    extern __shared__ uint32_t sm[];   // 4 stages x 6144 u32
    const int tid = threadIdx.x;
    const int lane = tid & 31, wid = tid >> 5;
    const int warpM = wid & 3, warpN = wid >> 2;   // 4M x 2N
    const int nchunk = blockIdx.x;     // 0..7
    const int mtile  = blockIdx.y;     // 0..195
    const int m0g = mtile * 128;
    const int g = lane >> 2, tig = lane & 3;

    const uint32_t smbase = (uint32_t)__cvta_generic_to_shared(sm);

    float acc[2][4][4];
#pragma unroll
    for (int i = 0; i < 2; i++)
#pragma unroll
        for (int j = 0; j < 4; j++)
#pragma unroll
            for (int q = 0; q < 4; q++) acc[i][j][q] = 0.f;

    // ---- async load of k-step ks into stage st: 1536 x 16B, 6/thread ----
    auto issue = [&](int ks, int st) {
        const uint32_t so = smbase + (uint32_t)(st * STAGE_U32) * 4u;
#pragma unroll
        for (int i = 0; i < 6; i++) {
            int c = i * 256 + tid;           // 0..1535
            uint32_t dst;
            const void* src;
            if (c < 1024) {                  // A raw fp32: row(128) x col16(8)
                int row = c >> 3, c16 = c & 7;
                src = enc + (size_t)(m0g + row) * ENC_ + ks * 32 + c16 * 4;
                dst = so + (uint32_t)(row * 32 + ((c16 ^ (row & 7)) * 4)) * 4u;
            } else {                         // B: fn8 kf2 hilo2 sub16
                int d = c - 1024;
                int fn = d >> 6, kf = (d >> 5) & 1, hilo = (d >> 4) & 1, sub = d & 15;
                const uint32_t* base = hilo ? g_Blo : g_Bhi;
                src = base + (((size_t)(nchunk * 8 + fn) * KF_TOT + (ks * 2 + kf)) * 64 + sub * 4);
                dst = so + (uint32_t)(4096 + ((fn * 2 + kf) * 2 + hilo) * 64 + sub * 4) * 4u;
            }
            cp16(dst, src);
        }
        cp_commit();
    };

    issue(0, 0);
    issue(1, 1);
    issue(2, 2);

    for (int s = 0; s < NKS; s++) {
        const int st = s & (NSTAGE - 1);
        if (s <= NKS - 3)      cp_wait<2>();
        else if (s == NKS - 2) cp_wait<1>();
        else                   cp_wait<0>();
        __syncthreads();

        const int sb = st * STAGE_U32;
#pragma unroll
        for (int kf = 0; kf < 2; kf++) {
            // ---- A fragments: LDS.64 fp32 pair -> split hi/lo ----
            uint32_t ahi[2][4], alo[2][4];
#pragma unroll
            for (int fm = 0; fm < 2; fm++) {
                int fmAbs = warpM * 2 + fm;
#pragma unroll
                for (int r = 0; r < 4; r++) {
                    int row = fmAbs * 16 + (r & 1) * 8 + g;
                    int c16 = kf * 4 + (r >> 1) * 2 + (tig >> 1);
                    int idx = sb + row * 32 + ((c16 ^ g) * 4) + (tig & 1) * 2;
                    float2 f = *reinterpret_cast<const float2*>(&sm[idx]);
                    uint32_t h = cvt2bf(f.y, f.x);
                    float r0 = f.x - __uint_as_float(h << 16);
                    float r1 = f.y - __uint_as_float(h & 0xFFFF0000u);
                    ahi[fm][r] = h;
                    alo[fm][r] = cvt2bf(r1, r0);
                }
            }
            // ---- B fragments (prepacked) ----
            uint32_t b[4][2][2];   // [fn][hilo][reg]
#pragma unroll
            for (int fn = 0; fn < 4; fn++) {
                int fnAbs = warpN * 4 + fn;
#pragma unroll
                for (int h = 0; h < 2; h++) {
                    int off = sb + 4096 + ((fnAbs * 2 + kf) * 2 + h) * 64 + lane;
#pragma unroll
                    for (int r = 0; r < 2; r++) b[fn][h][r] = sm[off + r * 32];
                }
            }
            // ---- term-major mma: RAW distance 8 per accumulator ----
#pragma unroll
            for (int fm = 0; fm < 2; fm++)
#pragma unroll
                for (int fn = 0; fn < 4; fn++)
                    mma16816(acc[fm][fn], ahi[fm], b[fn][0]);   // hi*hi
#pragma unroll
            for (int fm = 0; fm < 2; fm++)
#pragma unroll
                for (int fn = 0; fn < 4; fn++)
                    mma16816(acc[fm][fn], alo[fm], b[fn][0]);   // lo*hi
#pragma unroll
            for (int fm = 0; fm < 2; fm++)
#pragma unroll
                for (int fn = 0; fn < 4; fn++)
                    mma16816(acc[fm][fn], ahi[fm], b[fn][1]);   // hi*lo
        }
        if (s + 3 < NKS) issue(s + 3, (s + 3) & (NSTAGE - 1));
    }

    // ---- fused epilogue ----
    float ep[2][2] = {{0.f, 0.f}, {0.f, 0.f}};
#pragma unroll
    for (int fm = 0; fm < 2; fm++) {
        int r0 = warpM * 32 + fm * 16 + g;
        int b0 = (m0g + r0) / N_;
        int b1 = (m0g + r0 + 8) / N_;
#pragma unroll
        for (int fn = 0; fn < 4; fn++) {
            int a0i = nchunk * 64 + warpN * 32 + fn * 8 + tig * 2;
            int a1i = a0i + 1;
            float w0 = Wfull[a0i], w1 = Wfull[a1i];
            float be0 = benc[a0i], be1 = benc[a1i];
            float t00 = g_att2[b0 * ATT_ + a0i];
            float t01 = g_att2[b0 * ATT_ + a1i];
            float t10 = g_att2[b1 * ATT_ + a0i];
            float t11 = g_att2[b1 * ATT_ + a1i];
            ep[fm][0] += fmaxf(acc[fm][fn][0] + be0 + t00, 0.f) * w0;
            ep[fm][0] += fmaxf(acc[fm][fn][1] + be1 + t01, 0.f) * w1;
            ep[fm][1] += fmaxf(acc[fm][fn][2] + be0 + t10, 0.f) * w0;
            ep[fm][1] += fmaxf(acc[fm][fn][3] + be1 + t11, 0.f) * w1;
        }
    }
#pragma unroll
    for (int off = 1; off <= 2; off <<= 1)
#pragma unroll
        for (int fm = 0; fm < 2; fm++) {
            ep[fm][0] += __shfl_xor_sync(0xffffffffu, ep[fm][0], off);
            ep[fm][1] += __shfl_xor_sync(0xffffffffu, ep[fm][1], off);
        }

    __syncthreads();                              // all warps past stage reads
    float* e_red = reinterpret_cast<float*>(sm);  // [128][2]
    if (tig == 0) {
#pragma unroll
        for (int fm = 0; fm < 2; fm++) {
            int r0 = warpM * 32 + fm * 16 + g;
            e_red[r0 * 2 + warpN]       = ep[fm][0];
            e_red[(r0 + 8) * 2 + warpN] = ep[fm][1];
        }
    }
    __syncthreads();
    if (tid < 128)
        g_epart[(size_t)(m0g + tid) * 8 + nchunk] = e_red[tid * 2] + e_red[tid * 2 + 1];
}

// ============================================================
// Kernel 3: softmax over n
// ============================================================
__global__ void softmax_kernel(float* __restrict__ out_alpha,
                               const float* __restrict__ bfull_p) {
    __shared__ float e_s[N_];
    __shared__ float red[256];
    int b = blockIdx.x, tid = threadIdx.x;
    float bfull = *bfull_p;

    float ev = -INFINITY;
    if (tid < N_) {
        const float* p = &g_epart[(size_t)(b * N_ + tid) * 8];
        float s = bfull;
#pragma unroll
        for (int c = 0; c < 8; c++) s += p[c];
        e_s[tid] = s; ev = s;
    }
    red[tid] = ev; __syncthreads();
#pragma unroll
    for (int off = 128; off > 0; off >>= 1) {
        if (tid < off) red[tid] = fmaxf(red[tid], red[tid + off]);
        __syncthreads();
    }
    float mx = red[0]; __syncthreads();
    float ex = 0.f;
    if (tid < N_) { ex = expf(e_s[tid] - mx); e_s[tid] = ex; }
    red[tid] = ex; __syncthreads();
#pragma unroll
    for (int off = 128; off > 0; off >>= 1) {
        if (tid < off) red[tid] += red[tid + off];
        __syncthreads();
    }
    float inv = 1.f / red[0];
    if (tid < N_) out_alpha[b * N_ + tid] = e_s[tid] * inv;
}

// ============================================================
// Kernel 4: awe[b][e] = sum_n enc[b][n][e] * alpha[b][n]  (float4)
// ============================================================
__global__ void awe_kernel(const float* __restrict__ enc,
                           const float* __restrict__ alpha,
                           float* __restrict__ out) {
    __shared__ float al[N_];
    int b = blockIdx.y;
    int e0 = (blockIdx.x * 256 + threadIdx.x) * 4;   // grid.x = 2
    if (threadIdx.x < N_) al[threadIdx.x] = alpha[b * N_ + threadIdx.x];
    __syncthreads();

    const float4* p = reinterpret_cast<const float4*>(enc + (size_t)b * N_ * ENC_ + e0);
    float4 acc = make_float4(0.f, 0.f, 0.f, 0.f);
#pragma unroll 4
    for (int n = 0; n < N_; n++) {
        float4 v = p[(size_t)n * (ENC_ / 4)];
        float a = al[n];
        acc.x += a * v.x; acc.y += a * v.y;
        acc.z += a * v.z; acc.w += a * v.w;
    }
    *reinterpret_cast<float4*>(out + (size_t)b * ENC_ + e0) = acc;
}

// ============================================================
extern "C" void kernel_launch(void* const* d_in, const int* in_sizes, int n_in,
                              void* d_out, int out_size) {
    const float* enc   = (const float*)d_in[0];
    const float* dech  = (const float*)d_in[1];
    const float* Wenc  = (const float*)d_in[2];
    const float* benc  = (const float*)d_in[3];
    const float* Wdec  = (const float*)d_in[4];
    const float* bdec  = (const float*)d_in[5];
    const float* Wfull = (const float*)d_in[6];
    const float* bfull = (const float*)d_in[7];

    float* out       = (float*)d_out;
    float* out_awe   = out;
    float* out_alpha = out + (size_t)B_ * ENC_;

    cudaFuncSetAttribute(gemm_e_kernel,
                         cudaFuncAttributeMaxDynamicSharedMemorySize, SMEM_BYTES);

    att2_kernel<<<B_, ATT_>>>(dech, Wdec, bdec);
    prepackB<<<FN_TOT * KF_TOT * 64 / 256, 256>>>(Wenc);

    dim3 g2(8, 196);                           // nchunk fastest -> A L2 reuse
    gemm_e_kernel<<<g2, 256, SMEM_BYTES>>>(enc, benc, Wfull);

    softmax_kernel<<<B_, 256>>>(out_alpha, bfull);

    dim3 g4(2, B_);
    awe_kernel<<<g4, 256>>>(enc, out_alpha, out_awe);
}

// round 6
// speedup vs baseline: 3.3688x; 1.3239x over previous
#include <cuda_runtime.h>
#include <cuda_fp16.h>
#include <stdint.h>
#include <math.h>

#define B_    128
#define N_    196
#define ENC_  2048
#define DEC_  512
#define ATT_  512
#define M_    (B_ * N_)          // 25088 rows
#define FM_TOT (M_ / 16)         // 1568 m-fragments
#define KF_TOT (ENC_ / 16)       // 128 k16 fragments
#define FN_TOT (ATT_ / 8)        // 64  n8 fragments

// gemm tiling: block 128m x 64n x 32k, 4-stage cp.async, 2 CTAs/SM
#define NKS        64            // k-steps of 32
#define STAGE_U32  4096          // A 2048 + B 2048 u32 per stage (16KB)
#define NSTAGE     4
#define SMEM_BYTES (NSTAGE * STAGE_U32 * 4)   // 65536

// ---- scratch (__device__ globals: sanctioned no-alloc workaround) ----
__device__ float    g_att2[B_ * ATT_];
__device__ float    g_epart[M_ * 8];
__device__ uint32_t g_Af [FM_TOT * KF_TOT * 128];  // A fp16, frag-major [fm][kf][lane][reg4]
__device__ uint32_t g_Bhi[FN_TOT * KF_TOT * 64];   // B hi fp16 [fn][kf][lane][reg2]
__device__ uint32_t g_Blo[FN_TOT * KF_TOT * 64];   // B lo fp16

// ============================================================
// helpers
// ============================================================
__device__ __forceinline__ uint32_t pack_h2(__half lo, __half hi) {
    __half2 p; p.x = lo; p.y = hi;       // .x = low 16 bits (lower k index)
    return *reinterpret_cast<uint32_t*>(&p);
}
__device__ __forceinline__ void cp16(uint32_t saddr, const void* g) {
    asm volatile("cp.async.cg.shared.global [%0], [%1], 16;\n" :: "r"(saddr), "l"(g));
}
__device__ __forceinline__ void cp_commit() { asm volatile("cp.async.commit_group;\n"); }
template <int NN> __device__ __forceinline__ void cp_wait() {
    asm volatile("cp.async.wait_group %0;\n" :: "n"(NN));
}
__device__ __forceinline__ void mma16816(float c[4], const uint32_t a[4], const uint32_t b[2]) {
    asm volatile(
        "mma.sync.aligned.m16n8k16.row.col.f32.f16.f16.f32 "
        "{%0,%1,%2,%3}, {%4,%5,%6,%7}, {%8,%9}, {%0,%1,%2,%3};\n"
        : "+f"(c[0]), "+f"(c[1]), "+f"(c[2]), "+f"(c[3])
        : "r"(a[0]), "r"(a[1]), "r"(a[2]), "r"(a[3]),
          "r"(b[0]), "r"(b[1]));
}

// ============================================================
// Kernel 1: att2 = decoder_hidden @ W_dec + b_dec   (fp32 exact)
// ============================================================
__global__ void att2_kernel(const float* __restrict__ dec,
                            const float* __restrict__ Wdec,
                            const float* __restrict__ bdec) {
    __shared__ float ds[DEC_];
    int b = blockIdx.x, a = threadIdx.x;
    ds[a] = dec[b * DEC_ + a];
    __syncthreads();
    float acc = bdec[a];
#pragma unroll 8
    for (int d = 0; d < DEC_; d++) acc += ds[d] * Wdec[d * ATT_ + a];
    g_att2[b * ATT_ + a] = acc;
}

// ============================================================
// Prepack A: enc fp32 -> single fp16, frag-major [fm][kf][lane][reg4]
//   reg r: row = fm*16 + (r&1)*8 + (lane>>2), k = kf*16 + (r>>1)*8 + (lane&3)*2
// ============================================================
__global__ void prepackA(const float* __restrict__ enc) {
    int idx = blockIdx.x * 256 + threadIdx.x;
    int reg  = idx & 3;
    int lane = (idx >> 2) & 31;
    int kf   = (idx >> 7) & (KF_TOT - 1);
    int fm   = idx >> 14;
    int m = fm * 16 + (reg & 1) * 8 + (lane >> 2);
    int k = kf * 16 + (reg >> 1) * 8 + (lane & 3) * 2;
    float2 v = *reinterpret_cast<const float2*>(enc + (size_t)m * ENC_ + k);
    g_Af[idx] = pack_h2(__float2half_rn(v.x), __float2half_rn(v.y));
}

// ============================================================
// Prepack B: W_enc [K][N] -> fp16 hi/lo, frag-major [fn][kf][lane][reg2]
//   reg r: k = kf*16 + r*8 + (lane&3)*2, n = fn*8 + (lane>>2)
// ============================================================
__global__ void prepackB(const float* __restrict__ Wenc) {
    int idx = blockIdx.x * 256 + threadIdx.x;
    int reg  = idx & 1;
    int lane = (idx >> 1) & 31;
    int kf   = (idx >> 6) & (KF_TOT - 1);
    int fn   = idx >> 13;
    int n = fn * 8 + (lane >> 2);
    int k = kf * 16 + reg * 8 + (lane & 3) * 2;
    float v0 = Wenc[(size_t)k * ATT_ + n];
    float v1 = Wenc[(size_t)(k + 1) * ATT_ + n];
    __half h0 = __float2half_rn(v0);
    __half h1 = __float2half_rn(v1);
    __half l0 = __float2half_rn(v0 - __half2float(h0));
    __half l1 = __float2half_rn(v1 - __half2float(h1));
    g_Bhi[idx] = pack_h2(h0, h1);
    g_Blo[idx] = pack_h2(l0, l1);
}

// ============================================================
// Kernel 2: HMMA GEMM (2-term fp16: ah*bh + ah*bl) + fused epilogue
//   block 128m x 64n x 32k; 8 warps (4M x 2N), warp tile 32x32
//   vectorized frag loads: A LDS.128, B LDS.64, conflict-free
//   grid (nchunk=8 fastest, mtile=196) for L2 reuse of A
// ============================================================
__global__ __launch_bounds__(256, 2)
void gemm_e_kernel(const float* __restrict__ benc,
                   const float* __restrict__ Wfull) {
    extern __shared__ uint32_t sm[];   // 4 stages x 4096 u32
    const int tid = threadIdx.x;
    const int lane = tid & 31, wid = tid >> 5;
    const int warpM = wid & 3, warpN = wid >> 2;   // 4M x 2N
    const int nchunk = blockIdx.x;     // 0..7
    const int mtile  = blockIdx.y;     // 0..195
    const int m0g = mtile * 128;
    const int g = lane >> 2, tig = lane & 3;

    const uint32_t smbase = (uint32_t)__cvta_generic_to_shared(sm);

    float acc[2][4][4];
#pragma unroll
    for (int i = 0; i < 2; i++)
#pragma unroll
        for (int j = 0; j < 4; j++)
#pragma unroll
            for (int q = 0; q < 4; q++) acc[i][j][q] = 0.f;

    // ---- async load of k-step ks into stage st: 1024 x 16B, 4/thread ----
    auto issue = [&](int ks, int st) {
        const uint32_t so = smbase + (uint32_t)(st * STAGE_U32) * 4u;
#pragma unroll
        for (int i = 0; i < 4; i++) {
            int c = i * 256 + tid;           // 0..1023
            uint32_t dst;
            const void* src;
            if (c < 512) {                   // A: fm8 kf2 lane32 (4 regs = 16B)
                int fm = c >> 6, kf = (c >> 5) & 1, ln = c & 31;
                src = g_Af + ((size_t)(mtile * 8 + fm) * KF_TOT + (ks * 2 + kf)) * 128 + ln * 4;
                dst = so + (uint32_t)((fm * 2 + kf) * 128 + ln * 4) * 4u;
            } else {                         // B: fn8 kf2 hilo2 q16 (4 u32 = 2 lanes)
                int d = c - 512;
                int fn = d >> 6, kf = (d >> 5) & 1, hilo = (d >> 4) & 1, q = d & 15;
                const uint32_t* base = hilo ? g_Blo : g_Bhi;
                src = base + ((size_t)(nchunk * 8 + fn) * KF_TOT + (ks * 2 + kf)) * 64 + q * 4;
                dst = so + (uint32_t)(2048 + ((fn * 2 + kf) * 2 + hilo) * 64 + q * 4) * 4u;
            }
            cp16(dst, src);
        }
        cp_commit();
    };

    issue(0, 0);
    issue(1, 1);
    issue(2, 2);

    for (int s = 0; s < NKS; s++) {
        const int st = s & (NSTAGE - 1);
        if (s <= NKS - 3)      cp_wait<2>();
        else if (s == NKS - 2) cp_wait<1>();
        else                   cp_wait<0>();
        __syncthreads();

        const int sb = st * STAGE_U32;
#pragma unroll
        for (int kf = 0; kf < 2; kf++) {
            // A fragments: one LDS.128 per fm
            uint32_t a[2][4];
#pragma unroll
            for (int fm = 0; fm < 2; fm++) {
                int fmAbs = warpM * 2 + fm;
                uint4 v = *reinterpret_cast<const uint4*>(
                    &sm[sb + (fmAbs * 2 + kf) * 128 + lane * 4]);
                a[fm][0] = v.x; a[fm][1] = v.y; a[fm][2] = v.z; a[fm][3] = v.w;
            }
            // B fragments: one LDS.64 per (fn, hilo)
            uint32_t b[4][2][2];
#pragma unroll
            for (int fn = 0; fn < 4; fn++) {
                int fnAbs = warpN * 4 + fn;
#pragma unroll
                for (int h = 0; h < 2; h++) {
                    uint2 v = *reinterpret_cast<const uint2*>(
                        &sm[sb + 2048 + ((fnAbs * 2 + kf) * 2 + h) * 64 + lane * 2]);
                    b[fn][h][0] = v.x; b[fn][h][1] = v.y;
                }
            }
            // term-major: RAW distance 8 per accumulator
#pragma unroll
            for (int fm = 0; fm < 2; fm++)
#pragma unroll
                for (int fn = 0; fn < 4; fn++)
                    mma16816(acc[fm][fn], a[fm], b[fn][0]);   // a*bh
#pragma unroll
            for (int fm = 0; fm < 2; fm++)
#pragma unroll
                for (int fn = 0; fn < 4; fn++)
                    mma16816(acc[fm][fn], a[fm], b[fn][1]);   // a*bl
        }
        if (s + 3 < NKS) issue(s + 3, (s + 3) & (NSTAGE - 1));
    }

    // ---- fused epilogue: v = relu(acc + b_enc + att2); e += v * W_full ----
    float ep[2][2] = {{0.f, 0.f}, {0.f, 0.f}};
#pragma unroll
    for (int fm = 0; fm < 2; fm++) {
        int r0 = warpM * 32 + fm * 16 + g;
        int b0 = (m0g + r0) / N_;
        int b1 = (m0g + r0 + 8) / N_;
#pragma unroll
        for (int fn = 0; fn < 4; fn++) {
            int a0i = nchunk * 64 + warpN * 32 + fn * 8 + tig * 2;
            int a1i = a0i + 1;
            float w0 = Wfull[a0i], w1 = Wfull[a1i];
            float be0 = benc[a0i], be1 = benc[a1i];
            float t00 = g_att2[b0 * ATT_ + a0i];
            float t01 = g_att2[b0 * ATT_ + a1i];
            float t10 = g_att2[b1 * ATT_ + a0i];
            float t11 = g_att2[b1 * ATT_ + a1i];
            ep[fm][0] += fmaxf(acc[fm][fn][0] + be0 + t00, 0.f) * w0;
            ep[fm][0] += fmaxf(acc[fm][fn][1] + be1 + t01, 0.f) * w1;
            ep[fm][1] += fmaxf(acc[fm][fn][2] + be0 + t10, 0.f) * w0;
            ep[fm][1] += fmaxf(acc[fm][fn][3] + be1 + t11, 0.f) * w1;
        }
    }
#pragma unroll
    for (int off = 1; off <= 2; off <<= 1)
#pragma unroll
        for (int fm = 0; fm < 2; fm++) {
            ep[fm][0] += __shfl_xor_sync(0xffffffffu, ep[fm][0], off);
            ep[fm][1] += __shfl_xor_sync(0xffffffffu, ep[fm][1], off);
        }

    __syncthreads();                              // all warps past stage reads
    float* e_red = reinterpret_cast<float*>(sm);  // [128][2]
    if (tig == 0) {
#pragma unroll
        for (int fm = 0; fm < 2; fm++) {
            int r0 = warpM * 32 + fm * 16 + g;
            e_red[r0 * 2 + warpN]       = ep[fm][0];
            e_red[(r0 + 8) * 2 + warpN] = ep[fm][1];
        }
    }
    __syncthreads();
    if (tid < 128)
        g_epart[(size_t)(m0g + tid) * 8 + nchunk] = e_red[tid * 2] + e_red[tid * 2 + 1];
}

// ============================================================
// Kernel 3: softmax over n
// ============================================================
__global__ void softmax_kernel(float* __restrict__ out_alpha,
                               const float* __restrict__ bfull_p) {
    __shared__ float e_s[N_];
    __shared__ float red[256];
    int b = blockIdx.x, tid = threadIdx.x;
    float bfull = *bfull_p;

    float ev = -INFINITY;
    if (tid < N_) {
        const float* p = &g_epart[(size_t)(b * N_ + tid) * 8];
        float s = bfull;
#pragma unroll
        for (int c = 0; c < 8; c++) s += p[c];
        e_s[tid] = s; ev = s;
    }
    red[tid] = ev; __syncthreads();
#pragma unroll
    for (int off = 128; off > 0; off >>= 1) {
        if (tid < off) red[tid] = fmaxf(red[tid], red[tid + off]);
        __syncthreads();
    }
    float mx = red[0]; __syncthreads();
    float ex = 0.f;
    if (tid < N_) { ex = expf(e_s[tid] - mx); e_s[tid] = ex; }
    red[tid] = ex; __syncthreads();
#pragma unroll
    for (int off = 128; off > 0; off >>= 1) {
        if (tid < off) red[tid] += red[tid + off];
        __syncthreads();
    }
    float inv = 1.f / red[0];
    if (tid < N_) out_alpha[b * N_ + tid] = e_s[tid] * inv;
}

// ============================================================
// Kernel 4: awe[b][e] = sum_n enc[b][n][e] * alpha[b][n]  (float4, fp32)
// ============================================================
__global__ void awe_kernel(const float* __restrict__ enc,
                           const float* __restrict__ alpha,
                           float* __restrict__ out) {
    __shared__ float al[N_];
    int b = blockIdx.y;
    int e0 = (blockIdx.x * 256 + threadIdx.x) * 4;   // grid.x = 2
    if (threadIdx.x < N_) al[threadIdx.x] = alpha[b * N_ + threadIdx.x];
    __syncthreads();

    const float4* p = reinterpret_cast<const float4*>(enc + (size_t)b * N_ * ENC_ + e0);
    float4 acc = make_float4(0.f, 0.f, 0.f, 0.f);
#pragma unroll 4
    for (int n = 0; n < N_; n++) {
        float4 v = p[(size_t)n * (ENC_ / 4)];
        float a = al[n];
        acc.x += a * v.x; acc.y += a * v.y;
        acc.z += a * v.z; acc.w += a * v.w;
    }
    *reinterpret_cast<float4*>(out + (size_t)b * ENC_ + e0) = acc;
}

// ============================================================
extern "C" void kernel_launch(void* const* d_in, const int* in_sizes, int n_in,
                              void* d_out, int out_size) {
    const float* enc   = (const float*)d_in[0];
    const float* dech  = (const float*)d_in[1];
    const float* Wenc  = (const float*)d_in[2];
    const float* benc  = (const float*)d_in[3];
    const float* Wdec  = (const float*)d_in[4];
    const float* bdec  = (const float*)d_in[5];
    const float* Wfull = (const float*)d_in[6];
    const float* bfull = (const float*)d_in[7];

    float* out       = (float*)d_out;
    float* out_awe   = out;
    float* out_alpha = out + (size_t)B_ * ENC_;

    cudaFuncSetAttribute(gemm_e_kernel,
                         cudaFuncAttributeMaxDynamicSharedMemorySize, SMEM_BYTES);

    att2_kernel<<<B_, ATT_>>>(dech, Wdec, bdec);
    prepackA<<<FM_TOT * KF_TOT * 128 / 256, 256>>>(enc);
    prepackB<<<FN_TOT * KF_TOT * 64 / 256, 256>>>(Wenc);

    dim3 g2(8, 196);                           // nchunk fastest -> A L2 reuse
    gemm_e_kernel<<<g2, 256, SMEM_BYTES>>>(benc, Wfull);

    softmax_kernel<<<B_, 256>>>(out_alpha, bfull);

    dim3 g4(2, B_);
    awe_kernel<<<g4, 256>>>(enc, out_alpha, out_awe);
}

// round 7
// speedup vs baseline: 4.7203x; 1.4012x over previous
#include <cuda_runtime.h>
#include <cuda_fp16.h>
#include <stdint.h>
#include <math.h>

#define B_    128
#define N_    196
#define ENC_  2048
#define DEC_  512
#define ATT_  512
#define M_    (B_ * N_)          // 25088 rows
#define FM_TOT (M_ / 16)         // 1568 m-fragments
#define KF_TOT (ENC_ / 16)       // 128 k16 fragments
#define FN_TOT (ATT_ / 8)        // 64  n8 fragments

// gemm tiling: block 128m x 128n x 64k, 3-stage cp.async, 2 CTAs/SM
#define NKS        32            // k-steps of 64
#define STAGE_U32  8192          // A 4096 + B 4096 u32 per stage (32KB)
#define NSTAGE     3
#define SMEM_BYTES (NSTAGE * STAGE_U32 * 4)   // 98304

// ---- scratch (__device__ globals: sanctioned no-alloc workaround) ----
__device__ float    g_att2[B_ * ATT_];
__device__ float    g_epart[M_ * 4];
__device__ uint32_t g_Af[FM_TOT * KF_TOT * 128];  // A fp16 frag-major [fm][kf][lane][reg4]
__device__ uint32_t g_Bf[FN_TOT * KF_TOT * 64];   // B fp16 frag-major [fn][kf][lane][reg2]

// ============================================================
// helpers
// ============================================================
__device__ __forceinline__ uint32_t pack_h2(__half lo, __half hi) {
    __half2 p; p.x = lo; p.y = hi;       // .x = low 16 bits (lower k index)
    return *reinterpret_cast<uint32_t*>(&p);
}
__device__ __forceinline__ void cp16(uint32_t saddr, const void* g) {
    asm volatile("cp.async.cg.shared.global [%0], [%1], 16;\n" :: "r"(saddr), "l"(g));
}
__device__ __forceinline__ void cp_commit() { asm volatile("cp.async.commit_group;\n"); }
template <int NN> __device__ __forceinline__ void cp_wait() {
    asm volatile("cp.async.wait_group %0;\n" :: "n"(NN));
}
__device__ __forceinline__ void mma16816(float c[4], const uint32_t a[4], const uint32_t b[2]) {
    asm volatile(
        "mma.sync.aligned.m16n8k16.row.col.f32.f16.f16.f32 "
        "{%0,%1,%2,%3}, {%4,%5,%6,%7}, {%8,%9}, {%0,%1,%2,%3};\n"
        : "+f"(c[0]), "+f"(c[1]), "+f"(c[2]), "+f"(c[3])
        : "r"(a[0]), "r"(a[1]), "r"(a[2]), "r"(a[3]),
          "r"(b[0]), "r"(b[1]));
}

// ============================================================
// Kernel 1: att2 = decoder_hidden @ W_dec + b_dec   (fp32 exact)
// ============================================================
__global__ void att2_kernel(const float* __restrict__ dec,
                            const float* __restrict__ Wdec,
                            const float* __restrict__ bdec) {
    __shared__ float ds[DEC_];
    int b = blockIdx.x, a = threadIdx.x;
    ds[a] = dec[b * DEC_ + a];
    __syncthreads();
    float acc = bdec[a];
#pragma unroll 8
    for (int d = 0; d < DEC_; d++) acc += ds[d] * Wdec[d * ATT_ + a];
    g_att2[b * ATT_ + a] = acc;
}

// ============================================================
// Prepack A: enc fp32 -> single fp16, frag-major [fm][kf][lane][reg4]
// ============================================================
__global__ void prepackA(const float* __restrict__ enc) {
    int idx = blockIdx.x * 256 + threadIdx.x;
    int reg  = idx & 3;
    int lane = (idx >> 2) & 31;
    int kf   = (idx >> 7) & (KF_TOT - 1);
    int fm   = idx >> 14;
    int m = fm * 16 + (reg & 1) * 8 + (lane >> 2);
    int k = kf * 16 + (reg >> 1) * 8 + (lane & 3) * 2;
    float2 v = *reinterpret_cast<const float2*>(enc + (size_t)m * ENC_ + k);
    g_Af[idx] = pack_h2(__float2half_rn(v.x), __float2half_rn(v.y));
}

// ============================================================
// Prepack B: W_enc [K][N] -> single fp16, frag-major [fn][kf][lane][reg2]
// ============================================================
__global__ void prepackB(const float* __restrict__ Wenc) {
    int idx = blockIdx.x * 256 + threadIdx.x;
    int reg  = idx & 1;
    int lane = (idx >> 1) & 31;
    int kf   = (idx >> 6) & (KF_TOT - 1);
    int fn   = idx >> 13;
    int n = fn * 8 + (lane >> 2);
    int k = kf * 16 + reg * 8 + (lane & 3) * 2;
    float v0 = Wenc[(size_t)k * ATT_ + n];
    float v1 = Wenc[(size_t)(k + 1) * ATT_ + n];
    g_Bf[idx] = pack_h2(__float2half_rn(v0), __float2half_rn(v1));
}

// ============================================================
// Kernel 2: HMMA GEMM (1-term fp16) + fused epilogue
//   block 128m x 128n x 64k; 8 warps (4M x 2N), warp tile 32x64
//   grid (nchunk=4 fastest, mtile=196) for L2 reuse of A
// ============================================================
__global__ __launch_bounds__(256, 2)
void gemm_e_kernel(const float* __restrict__ benc,
                   const float* __restrict__ Wfull) {
    extern __shared__ uint32_t sm[];   // 3 stages x 8192 u32
    const int tid = threadIdx.x;
    const int lane = tid & 31, wid = tid >> 5;
    const int warpM = wid & 3, warpN = wid >> 2;   // 4M x 2N
    const int nchunk = blockIdx.x;     // 0..3
    const int mtile  = blockIdx.y;     // 0..195
    const int m0g = mtile * 128;
    const int g = lane >> 2, tig = lane & 3;

    const uint32_t smbase = (uint32_t)__cvta_generic_to_shared(sm);

    float acc[2][8][4];
#pragma unroll
    for (int i = 0; i < 2; i++)
#pragma unroll
        for (int j = 0; j < 8; j++)
#pragma unroll
            for (int q = 0; q < 4; q++) acc[i][j][q] = 0.f;

    // ---- async load of k-step ks (64 k) into stage st: 2048 x 16B ----
    auto issue = [&](int ks, int st) {
        const uint32_t so = smbase + (uint32_t)(st * STAGE_U32) * 4u;
#pragma unroll
        for (int i = 0; i < 8; i++) {
            int c = i * 256 + tid;           // 0..2047
            uint32_t dst;
            const void* src;
            if (c < 1024) {                  // A: fm8 kf4 lane32
                int fm = c >> 7, kf = (c >> 5) & 3, ln = c & 31;
                src = g_Af + ((size_t)(mtile * 8 + fm) * KF_TOT + (ks * 4 + kf)) * 128 + ln * 4;
                dst = so + (uint32_t)((fm * 4 + kf) * 128 + ln * 4) * 4u;
            } else {                         // B: fn16 kf4 q16
                int d = c - 1024;
                int fn = d >> 6, kf = (d >> 4) & 3, q = d & 15;
                src = g_Bf + ((size_t)(nchunk * 16 + fn) * KF_TOT + (ks * 4 + kf)) * 64 + q * 4;
                dst = so + (uint32_t)(4096 + (fn * 4 + kf) * 64 + q * 4) * 4u;
            }
            cp16(dst, src);
        }
        cp_commit();
    };

    issue(0, 0);
    issue(1, 1);

    for (int s = 0; s < NKS; s++) {
        const int st = s % NSTAGE;
        if (s + 1 < NKS) cp_wait<1>(); else cp_wait<0>();
        __syncthreads();

        const int sb = st * STAGE_U32;
#pragma unroll
        for (int kf = 0; kf < 4; kf++) {
            // A fragments: one LDS.128 per fm
            uint32_t a[2][4];
#pragma unroll
            for (int fm = 0; fm < 2; fm++) {
                int fmAbs = warpM * 2 + fm;
                uint4 v = *reinterpret_cast<const uint4*>(
                    &sm[sb + (fmAbs * 4 + kf) * 128 + lane * 4]);
                a[fm][0] = v.x; a[fm][1] = v.y; a[fm][2] = v.z; a[fm][3] = v.w;
            }
            // B fragments: one LDS.64 per fn
            uint32_t b[8][2];
#pragma unroll
            for (int fn = 0; fn < 8; fn++) {
                int fnAbs = warpN * 8 + fn;
                uint2 v = *reinterpret_cast<const uint2*>(
                    &sm[sb + 4096 + (fnAbs * 4 + kf) * 64 + lane * 2]);
                b[fn][0] = v.x; b[fn][1] = v.y;
            }
#pragma unroll
            for (int fm = 0; fm < 2; fm++)
#pragma unroll
                for (int fn = 0; fn < 8; fn++)
                    mma16816(acc[fm][fn], a[fm], b[fn]);
        }
        if (s + 2 < NKS) issue(s + 2, (s + 2) % NSTAGE);
    }

    // ---- fused epilogue: v = relu(acc + b_enc + att2); e += v * W_full ----
    float ep[2][2] = {{0.f, 0.f}, {0.f, 0.f}};
#pragma unroll
    for (int fm = 0; fm < 2; fm++) {
        int r0 = warpM * 32 + fm * 16 + g;
        int b0 = (m0g + r0) / N_;
        int b1 = (m0g + r0 + 8) / N_;
#pragma unroll
        for (int fn = 0; fn < 8; fn++) {
            int a0i = nchunk * 128 + warpN * 64 + fn * 8 + tig * 2;
            int a1i = a0i + 1;
            float w0 = Wfull[a0i], w1 = Wfull[a1i];
            float be0 = benc[a0i], be1 = benc[a1i];
            float t00 = g_att2[b0 * ATT_ + a0i];
            float t01 = g_att2[b0 * ATT_ + a1i];
            float t10 = g_att2[b1 * ATT_ + a0i];
            float t11 = g_att2[b1 * ATT_ + a1i];
            ep[fm][0] += fmaxf(acc[fm][fn][0] + be0 + t00, 0.f) * w0;
            ep[fm][0] += fmaxf(acc[fm][fn][1] + be1 + t01, 0.f) * w1;
            ep[fm][1] += fmaxf(acc[fm][fn][2] + be0 + t10, 0.f) * w0;
            ep[fm][1] += fmaxf(acc[fm][fn][3] + be1 + t11, 0.f) * w1;
        }
    }
#pragma unroll
    for (int off = 1; off <= 2; off <<= 1)
#pragma unroll
        for (int fm = 0; fm < 2; fm++) {
            ep[fm][0] += __shfl_xor_sync(0xffffffffu, ep[fm][0], off);
            ep[fm][1] += __shfl_xor_sync(0xffffffffu, ep[fm][1], off);
        }

    __syncthreads();                              // all warps past stage reads
    float* e_red = reinterpret_cast<float*>(sm);  // [128][2]
    if (tig == 0) {
#pragma unroll
        for (int fm = 0; fm < 2; fm++) {
            int r0 = warpM * 32 + fm * 16 + g;
            e_red[r0 * 2 + warpN]       = ep[fm][0];
            e_red[(r0 + 8) * 2 + warpN] = ep[fm][1];
        }
    }
    __syncthreads();
    if (tid < 128)
        g_epart[(size_t)(m0g + tid) * 4 + nchunk] = e_red[tid * 2] + e_red[tid * 2 + 1];
}

// ============================================================
// Kernel 3: softmax over n
// ============================================================
__global__ void softmax_kernel(float* __restrict__ out_alpha,
                               const float* __restrict__ bfull_p) {
    __shared__ float e_s[N_];
    __shared__ float red[256];
    int b = blockIdx.x, tid = threadIdx.x;
    float bfull = *bfull_p;

    float ev = -INFINITY;
    if (tid < N_) {
        const float* p = &g_epart[(size_t)(b * N_ + tid) * 4];
        float s = bfull + p[0] + p[1] + p[2] + p[3];
        e_s[tid] = s; ev = s;
    }
    red[tid] = ev; __syncthreads();
#pragma unroll
    for (int off = 128; off > 0; off >>= 1) {
        if (tid < off) red[tid] = fmaxf(red[tid], red[tid + off]);
        __syncthreads();
    }
    float mx = red[0]; __syncthreads();
    float ex = 0.f;
    if (tid < N_) { ex = expf(e_s[tid] - mx); e_s[tid] = ex; }
    red[tid] = ex; __syncthreads();
#pragma unroll
    for (int off = 128; off > 0; off >>= 1) {
        if (tid < off) red[tid] += red[tid + off];
        __syncthreads();
    }
    float inv = 1.f / red[0];
    if (tid < N_) out_alpha[b * N_ + tid] = e_s[tid] * inv;
}

// ============================================================
// Kernel 4: awe[b][e] = sum_n enc[b][n][e] * alpha[b][n]
//   float4 + dual accumulator (2-way MLP over n and n+98)
// ============================================================
__global__ void awe_kernel(const float* __restrict__ enc,
                           const float* __restrict__ alpha,
                           float* __restrict__ out) {
    __shared__ float al[N_];
    int b = blockIdx.y;
    int e0 = (blockIdx.x * 256 + threadIdx.x) * 4;   // grid.x = 2
    if (threadIdx.x < N_) al[threadIdx.x] = alpha[b * N_ + threadIdx.x];
    __syncthreads();

    const float4* p = reinterpret_cast<const float4*>(enc + (size_t)b * N_ * ENC_ + e0);
    float4 acc0 = make_float4(0.f, 0.f, 0.f, 0.f);
    float4 acc1 = make_float4(0.f, 0.f, 0.f, 0.f);
#pragma unroll 7
    for (int n = 0; n < 98; n++) {
        float4 v0 = p[(size_t)n * (ENC_ / 4)];
        float4 v1 = p[(size_t)(n + 98) * (ENC_ / 4)];
        float a0 = al[n], a1 = al[n + 98];
        acc0.x += a0 * v0.x; acc0.y += a0 * v0.y;
        acc0.z += a0 * v0.z; acc0.w += a0 * v0.w;
        acc1.x += a1 * v1.x; acc1.y += a1 * v1.y;
        acc1.z += a1 * v1.z; acc1.w += a1 * v1.w;
    }
    float4 r;
    r.x = acc0.x + acc1.x; r.y = acc0.y + acc1.y;
    r.z = acc0.z + acc1.z; r.w = acc0.w + acc1.w;
    *reinterpret_cast<float4*>(out + (size_t)b * ENC_ + e0) = r;
}

// ============================================================
extern "C" void kernel_launch(void* const* d_in, const int* in_sizes, int n_in,
                              void* d_out, int out_size) {
    const float* enc   = (const float*)d_in[0];
    const float* dech  = (const float*)d_in[1];
    const float* Wenc  = (const float*)d_in[2];
    const float* benc  = (const float*)d_in[3];
    const float* Wdec  = (const float*)d_in[4];
    const float* bdec  = (const float*)d_in[5];
    const float* Wfull = (const float*)d_in[6];
    const float* bfull = (const float*)d_in[7];

    float* out       = (float*)d_out;
    float* out_awe   = out;
    float* out_alpha = out + (size_t)B_ * ENC_;

    cudaFuncSetAttribute(gemm_e_kernel,
                         cudaFuncAttributeMaxDynamicSharedMemorySize, SMEM_BYTES);

    att2_kernel<<<B_, ATT_>>>(dech, Wdec, bdec);
    prepackA<<<FM_TOT * KF_TOT * 128 / 256, 256>>>(enc);
    prepackB<<<FN_TOT * KF_TOT * 64 / 256, 256>>>(Wenc);

    dim3 g2(4, 196);                           // nchunk fastest -> A L2 reuse
    gemm_e_kernel<<<g2, 256, SMEM_BYTES>>>(benc, Wfull);

    softmax_kernel<<<B_, 256>>>(out_alpha, bfull);

    dim3 g4(2, B_);
    awe_kernel<<<g4, 256>>>(enc, out_alpha, out_awe);
}

// round 8
// speedup vs baseline: 5.5739x; 1.1808x over previous
#include <cuda_runtime.h>
#include <cuda_fp16.h>
#include <stdint.h>
#include <math.h>

#define B_    128
#define N_    196
#define ENC_  2048
#define DEC_  512
#define ATT_  512
#define M_    (B_ * N_)          // 25088 rows
#define KF_TOT (ENC_ / 16)       // 128 k16 fragments
#define FN_TOT (ATT_ / 8)        // 64  n8 fragments

// gemm tiling: block 128m x 128n x 64k, 2-stage, 2 CTAs/SM
// stage: A raw fp32 128x64 (32KB) + B fp16 frag-major (16KB) = 48KB
#define NKS        32            // k-steps of 64
#define STAGE_U32  12288         // 48KB per stage
#define SMEM_BYTES (2 * STAGE_U32 * 4)   // 98304

// ---- scratch (__device__ globals: sanctioned no-alloc workaround) ----
__device__ float    g_att2[B_ * ATT_];
__device__ float    g_epart[M_ * 4];
__device__ uint32_t g_Bf[FN_TOT * KF_TOT * 64];   // B fp16 frag-major, permuted k

// ============================================================
// helpers
// ============================================================
__device__ __forceinline__ uint32_t pack_h2(__half lo, __half hi) {
    __half2 p; p.x = lo; p.y = hi;       // .x = low 16 bits (lower k index)
    return *reinterpret_cast<uint32_t*>(&p);
}
__device__ __forceinline__ uint32_t cvt2h(float hi, float lo) {
    uint32_t r;
    asm("cvt.rn.f16x2.f32 %0, %1, %2;" : "=r"(r) : "f"(hi), "f"(lo));
    return r;
}
__device__ __forceinline__ void cp16(uint32_t saddr, const void* g) {
    asm volatile("cp.async.cg.shared.global [%0], [%1], 16;\n" :: "r"(saddr), "l"(g));
}
__device__ __forceinline__ void cp_commit() { asm volatile("cp.async.commit_group;\n"); }
template <int NN> __device__ __forceinline__ void cp_wait() {
    asm volatile("cp.async.wait_group %0;\n" :: "n"(NN));
}
__device__ __forceinline__ void mma16816(float c[4], const uint32_t a[4], const uint32_t b[2]) {
    asm volatile(
        "mma.sync.aligned.m16n8k16.row.col.f32.f16.f16.f32 "
        "{%0,%1,%2,%3}, {%4,%5,%6,%7}, {%8,%9}, {%0,%1,%2,%3};\n"
        : "+f"(c[0]), "+f"(c[1]), "+f"(c[2]), "+f"(c[3])
        : "r"(a[0]), "r"(a[1]), "r"(a[2]), "r"(a[3]),
          "r"(b[0]), "r"(b[1]));
}

// ============================================================
// Kernel 1: att2 = decoder_hidden @ W_dec + b_dec   (fp32 exact)
// ============================================================
__global__ void att2_kernel(const float* __restrict__ dec,
                            const float* __restrict__ Wdec,
                            const float* __restrict__ bdec) {
    __shared__ float ds[DEC_];
    int b = blockIdx.x, a = threadIdx.x;
    ds[a] = dec[b * DEC_ + a];
    __syncthreads();
    float acc = bdec[a];
#pragma unroll 8
    for (int d = 0; d < DEC_; d++) acc += ds[d] * Wdec[d * ATT_ + a];
    g_att2[b * ATT_ + a] = acc;
}

// ============================================================
// Prepack B: W_enc [K][N] -> fp16 frag-major with PERMUTED k layout
//   position (tig, kreg, elem) holds actual k = kf*16 + tig*4 + kreg*2 + elem
//   (A uses the same permutation -> mma result identical)
// ============================================================
__global__ void prepackB(const float* __restrict__ Wenc) {
    int idx = blockIdx.x * 256 + threadIdx.x;
    int reg  = idx & 1;                  // kreg
    int lane = (idx >> 1) & 31;
    int kf   = (idx >> 6) & (KF_TOT - 1);
    int fn   = idx >> 13;
    int n = fn * 8 + (lane >> 2);
    int k = kf * 16 + (lane & 3) * 4 + reg * 2;   // permuted
    float v0 = Wenc[(size_t)k * ATT_ + n];
    float v1 = Wenc[(size_t)(k + 1) * ATT_ + n];
    g_Bf[idx] = pack_h2(__float2half_rn(v0), __float2half_rn(v1));
}

// ============================================================
// Kernel 2: HMMA GEMM (1-term fp16, A converted in-kernel) + epilogue
//   block 128m x 128n x 64k; 8 warps (4M x 2N), warp tile 32x64
//   A: raw fp32 rows, additive-swizzled; cvt.rn.f16x2.f32 in regs
//   grid (nchunk=4 fastest, mtile=196) for L2 reuse of A
// ============================================================
__global__ __launch_bounds__(256, 2)
void gemm_e_kernel(const float* __restrict__ enc,
                   const float* __restrict__ benc,
                   const float* __restrict__ Wfull) {
    extern __shared__ uint32_t sm[];   // 2 stages x 12288 u32
    const int tid = threadIdx.x;
    const int lane = tid & 31, wid = tid >> 5;
    const int warpM = wid & 3, warpN = wid >> 2;   // 4M x 2N
    const int nchunk = blockIdx.x;     // 0..3
    const int mtile  = blockIdx.y;     // 0..195
    const int m0g = mtile * 128;
    const int g = lane >> 2, tig = lane & 3;

    const uint32_t smbase = (uint32_t)__cvta_generic_to_shared(sm);

    float acc[2][8][4];
#pragma unroll
    for (int i = 0; i < 2; i++)
#pragma unroll
        for (int j = 0; j < 8; j++)
#pragma unroll
            for (int q = 0; q < 4; q++) acc[i][j][q] = 0.f;

    // ---- async load of k-step ks (64 k): A raw fp32 + B fp16; 12/thread ----
    auto issue = [&](int ks, int st) {
        const uint32_t so = smbase + (uint32_t)(st * STAGE_U32) * 4u;
#pragma unroll
        for (int i = 0; i < 12; i++) {
            int c = i * 256 + tid;           // 0..3071
            uint32_t dst;
            const void* src;
            if (c < 2048) {                  // A: row(128) x chunk16(16B=4 fp32)
                int row = c >> 4, cc = c & 15;
                int csw = (cc + row * 4) & 15;
                src = enc + (size_t)(m0g + row) * ENC_ + ks * 64 + cc * 4;
                dst = so + (uint32_t)(row * 64 + csw * 4) * 4u;
            } else {                         // B: fn16 kf4 q16
                int d = c - 2048;
                int fn = d >> 6, kf = (d >> 4) & 3, q = d & 15;
                src = g_Bf + ((size_t)(nchunk * 16 + fn) * KF_TOT + (ks * 4 + kf)) * 64 + q * 4;
                dst = so + (uint32_t)(8192 + (fn * 4 + kf) * 64 + q * 4) * 4u;
            }
            cp16(dst, src);
        }
        cp_commit();
    };

    issue(0, 0);

    for (int s = 0; s < NKS; s++) {
        const int st = s & 1;
        cp_wait<0>();                 // only group s outstanding here
        __syncthreads();              // all warps done reading buffer s-1
        if (s + 1 < NKS) issue(s + 1, st ^ 1);

        const int sb = st * STAGE_U32;
#pragma unroll
        for (int kf = 0; kf < 4; kf++) {
            // A fragments: 2x LDS.128 fp32 + 4 cvt per fm
            uint32_t a[2][4];
#pragma unroll
            for (int fm = 0; fm < 2; fm++) {
                int rbase = (warpM * 2 + fm) * 16;
                int r0 = rbase + g, r1 = rbase + 8 + g;
                int c0 = ((kf * 4 + tig) + r0 * 4) & 15;
                int c1 = ((kf * 4 + tig) + r1 * 4) & 15;
                float4 f0 = *reinterpret_cast<const float4*>(&sm[sb + r0 * 64 + c0 * 4]);
                float4 f1 = *reinterpret_cast<const float4*>(&sm[sb + r1 * 64 + c1 * 4]);
                a[fm][0] = cvt2h(f0.y, f0.x);
                a[fm][1] = cvt2h(f1.y, f1.x);
                a[fm][2] = cvt2h(f0.w, f0.z);
                a[fm][3] = cvt2h(f1.w, f1.z);
            }
            // B fragments: one LDS.64 per fn
            uint32_t b[8][2];
#pragma unroll
            for (int fn = 0; fn < 8; fn++) {
                int fnAbs = warpN * 8 + fn;
                uint2 v = *reinterpret_cast<const uint2*>(
                    &sm[sb + 8192 + (fnAbs * 4 + kf) * 64 + lane * 2]);
                b[fn][0] = v.x; b[fn][1] = v.y;
            }
#pragma unroll
            for (int fm = 0; fm < 2; fm++)
#pragma unroll
                for (int fn = 0; fn < 8; fn++)
                    mma16816(acc[fm][fn], a[fm], b[fn]);
        }
    }

    // ---- fused epilogue: v = relu(acc + b_enc + att2); e += v * W_full ----
    float ep[2][2] = {{0.f, 0.f}, {0.f, 0.f}};
#pragma unroll
    for (int fm = 0; fm < 2; fm++) {
        int r0 = warpM * 32 + fm * 16 + g;
        int b0 = (m0g + r0) / N_;
        int b1 = (m0g + r0 + 8) / N_;
#pragma unroll
        for (int fn = 0; fn < 8; fn++) {
            int a0i = nchunk * 128 + warpN * 64 + fn * 8 + tig * 2;
            int a1i = a0i + 1;
            float w0 = Wfull[a0i], w1 = Wfull[a1i];
            float be0 = benc[a0i], be1 = benc[a1i];
            float t00 = g_att2[b0 * ATT_ + a0i];
            float t01 = g_att2[b0 * ATT_ + a1i];
            float t10 = g_att2[b1 * ATT_ + a0i];
            float t11 = g_att2[b1 * ATT_ + a1i];
            ep[fm][0] += fmaxf(acc[fm][fn][0] + be0 + t00, 0.f) * w0;
            ep[fm][0] += fmaxf(acc[fm][fn][1] + be1 + t01, 0.f) * w1;
            ep[fm][1] += fmaxf(acc[fm][fn][2] + be0 + t10, 0.f) * w0;
            ep[fm][1] += fmaxf(acc[fm][fn][3] + be1 + t11, 0.f) * w1;
        }
    }
#pragma unroll
    for (int off = 1; off <= 2; off <<= 1)
#pragma unroll
        for (int fm = 0; fm < 2; fm++) {
            ep[fm][0] += __shfl_xor_sync(0xffffffffu, ep[fm][0], off);
            ep[fm][1] += __shfl_xor_sync(0xffffffffu, ep[fm][1], off);
        }

    __syncthreads();                              // all warps past stage reads
    float* e_red = reinterpret_cast<float*>(sm);  // [128][2]
    if (tig == 0) {
#pragma unroll
        for (int fm = 0; fm < 2; fm++) {
            int r0 = warpM * 32 + fm * 16 + g;
            e_red[r0 * 2 + warpN]       = ep[fm][0];
            e_red[(r0 + 8) * 2 + warpN] = ep[fm][1];
        }
    }
    __syncthreads();
    if (tid < 128)
        g_epart[(size_t)(m0g + tid) * 4 + nchunk] = e_red[tid * 2] + e_red[tid * 2 + 1];
}

// ============================================================
// Kernel 3: softmax over n
// ============================================================
__global__ void softmax_kernel(float* __restrict__ out_alpha,
                               const float* __restrict__ bfull_p) {
    __shared__ float e_s[N_];
    __shared__ float red[256];
    int b = blockIdx.x, tid = threadIdx.x;
    float bfull = *bfull_p;

    float ev = -INFINITY;
    if (tid < N_) {
        const float* p = &g_epart[(size_t)(b * N_ + tid) * 4];
        float s = bfull + p[0] + p[1] + p[2] + p[3];
        e_s[tid] = s; ev = s;
    }
    red[tid] = ev; __syncthreads();
#pragma unroll
    for (int off = 128; off > 0; off >>= 1) {
        if (tid < off) red[tid] = fmaxf(red[tid], red[tid + off]);
        __syncthreads();
    }
    float mx = red[0]; __syncthreads();
    float ex = 0.f;
    if (tid < N_) { ex = expf(e_s[tid] - mx); e_s[tid] = ex; }
    red[tid] = ex; __syncthreads();
#pragma unroll
    for (int off = 128; off > 0; off >>= 1) {
        if (tid < off) red[tid] += red[tid + off];
        __syncthreads();
    }
    float inv = 1.f / red[0];
    if (tid < N_) out_alpha[b * N_ + tid] = e_s[tid] * inv;
}

// ============================================================
// Kernel 4: awe[b][e] = sum_n enc[b][n][e] * alpha[b][n]
//   float4 + dual accumulator (2-way MLP over n and n+98)
// ============================================================
__global__ void awe_kernel(const float* __restrict__ enc,
                           const float* __restrict__ alpha,
                           float* __restrict__ out) {
    __shared__ float al[N_];
    int b = blockIdx.y;
    int e0 = (blockIdx.x * 256 + threadIdx.x) * 4;   // grid.x = 2
    if (threadIdx.x < N_) al[threadIdx.x] = alpha[b * N_ + threadIdx.x];
    __syncthreads();

    const float4* p = reinterpret_cast<const float4*>(enc + (size_t)b * N_ * ENC_ + e0);
    float4 acc0 = make_float4(0.f, 0.f, 0.f, 0.f);
    float4 acc1 = make_float4(0.f, 0.f, 0.f, 0.f);
#pragma unroll 7
    for (int n = 0; n < 98; n++) {
        float4 v0 = p[(size_t)n * (ENC_ / 4)];
        float4 v1 = p[(size_t)(n + 98) * (ENC_ / 4)];
        float a0 = al[n], a1 = al[n + 98];
        acc0.x += a0 * v0.x; acc0.y += a0 * v0.y;
        acc0.z += a0 * v0.z; acc0.w += a0 * v0.w;
        acc1.x += a1 * v1.x; acc1.y += a1 * v1.y;
        acc1.z += a1 * v1.z; acc1.w += a1 * v1.w;
    }
    float4 r;
    r.x = acc0.x + acc1.x; r.y = acc0.y + acc1.y;
    r.z = acc0.z + acc1.z; r.w = acc0.w + acc1.w;
    *reinterpret_cast<float4*>(out + (size_t)b * ENC_ + e0) = r;
}

// ============================================================
extern "C" void kernel_launch(void* const* d_in, const int* in_sizes, int n_in,
                              void* d_out, int out_size) {
    const float* enc   = (const float*)d_in[0];
    const float* dech  = (const float*)d_in[1];
    const float* Wenc  = (const float*)d_in[2];
    const float* benc  = (const float*)d_in[3];
    const float* Wdec  = (const float*)d_in[4];
    const float* bdec  = (const float*)d_in[5];
    const float* Wfull = (const float*)d_in[6];
    const float* bfull = (const float*)d_in[7];

    float* out       = (float*)d_out;
    float* out_awe   = out;
    float* out_alpha = out + (size_t)B_ * ENC_;

    cudaFuncSetAttribute(gemm_e_kernel,
                         cudaFuncAttributeMaxDynamicSharedMemorySize, SMEM_BYTES);

    att2_kernel<<<B_, ATT_>>>(dech, Wdec, bdec);
    prepackB<<<FN_TOT * KF_TOT * 64 / 256, 256>>>(Wenc);

    dim3 g2(4, 196);                           // nchunk fastest -> A L2 reuse
    gemm_e_kernel<<<g2, 256, SMEM_BYTES>>>(enc, benc, Wfull);

    softmax_kernel<<<B_, 256>>>(out_alpha, bfull);

    dim3 g4(2, B_);
    awe_kernel<<<g4, 256>>>(enc, out_alpha, out_awe);
}